// round 12
// baseline (speedup 1.0000x reference)
#include <cuda_runtime.h>
#include <cuda_fp16.h>
#include <cstdint>
#include <cstddef>

#define NTOK 8192
#define HDIM 2048
#define NEXP 8
#define KCAP 1024
#define DFF  5461
#define NPAD 5504
#define NSLOT 8192   // NEXP * KCAP

// ---------------- device scratch (static, no allocations) ----------------
__device__ float  d_Sm [NEXP * NTOK];            // transposed: [expert][token]
__device__ int    d_cnt[NEXP];
__device__ int    d_idx[NSLOT];
__device__ float  d_G  [NSLOT];
__device__ __half d_Xg [(size_t)NSLOT * HDIM];   // gathered tokens fp16
__device__ __half d_Wg [(size_t)HDIM * NPAD];    // w_gate  [K=2048][N=5504] fp16
__device__ __half d_Wu [(size_t)HDIM * NPAD];    // w_up
__device__ __half d_Wd [(size_t)NPAD * HDIM];    // w_down  [K=5504][N=2048] fp16
__device__ __half d_Hh [(size_t)NSLOT * NPAD];   // silu(g)*up fp16

// ---------------- helpers ----------------
__device__ __forceinline__ uint32_t smem_u32(const void* p) {
    uint32_t a;
    asm("{ .reg .u64 t; cvta.to.shared.u64 t, %1; cvt.u32.u64 %0, t; }" : "=r"(a) : "l"(p));
    return a;
}
__device__ __forceinline__ void cpasync16(uint32_t dst, const void* src) {
    asm volatile("cp.async.cg.shared.global [%0], [%1], 16;" :: "r"(dst), "l"(src) : "memory");
}
#define CP_COMMIT()  asm volatile("cp.async.commit_group;" ::: "memory")
#define CP_WAIT1()   asm volatile("cp.async.wait_group 1;" ::: "memory")

__device__ __forceinline__ void ldm_x4(uint32_t* r, uint32_t a) {
    asm volatile("ldmatrix.sync.aligned.m8n8.x4.shared.b16 {%0,%1,%2,%3}, [%4];"
                 : "=r"(r[0]), "=r"(r[1]), "=r"(r[2]), "=r"(r[3]) : "r"(a));
}
__device__ __forceinline__ void ldm_x4_t(uint32_t* r, uint32_t a) {
    asm volatile("ldmatrix.sync.aligned.m8n8.x4.trans.shared.b16 {%0,%1,%2,%3}, [%4];"
                 : "=r"(r[0]), "=r"(r[1]), "=r"(r[2]), "=r"(r[3]) : "r"(a));
}
__device__ __forceinline__ void mma16816(float* c, const uint32_t* a, const uint32_t* b) {
    asm volatile(
        "mma.sync.aligned.m16n8k16.row.col.f32.f16.f16.f32 "
        "{%0,%1,%2,%3}, {%4,%5,%6,%7}, {%8,%9}, {%0,%1,%2,%3};"
        : "+f"(c[0]), "+f"(c[1]), "+f"(c[2]), "+f"(c[3])
        : "r"(a[0]), "r"(a[1]), "r"(a[2]), "r"(a[3]), "r"(b[0]), "r"(b[1]));
}

// ---------------- zero output (float4) ----------------
__global__ void zero_kernel(float4* p, size_t n4) {
    size_t i = (size_t)blockIdx.x * blockDim.x + threadIdx.x;
    if (i < n4) p[i] = make_float4(0.f, 0.f, 0.f, 0.f);
}

// ---------------- pad + fp16-convert weights ----------------
// Vectorized stores; scalar source loads for SEL 0/1 (DFF=5461 odd -> float4 misaligned).
template <int SEL>
__global__ void padconv_kernel(const float* __restrict__ src, int total8) {
    int i = blockIdx.x * blockDim.x + threadIdx.x;
    if (SEL == 0 && i < NEXP) d_cnt[i] = 0;
    if (i >= total8) return;
    __half h[8];
    if (SEL < 2) {
        int r = i / (NPAD / 8), c = (i - r * (NPAD / 8)) * 8;
        const float* s = src + (size_t)r * DFF + c;
#pragma unroll
        for (int q = 0; q < 8; q++)
            h[q] = (c + q < DFF) ? __float2half_rn(__ldg(s + q)) : __half(0.f);
        __half* dst = (SEL == 0) ? d_Wg : d_Wu;
        *(uint4*)(dst + (size_t)r * NPAD + c) = *(uint4*)h;
    } else {
        int r = i / (HDIM / 8), c = (i - r * (HDIM / 8)) * 8;
        if (r < DFF) {
            const float* s = src + (size_t)r * HDIM + c;
            float4 v0 = *(const float4*)s, v1 = *(const float4*)(s + 4);
            h[0]=__float2half_rn(v0.x); h[1]=__float2half_rn(v0.y);
            h[2]=__float2half_rn(v0.z); h[3]=__float2half_rn(v0.w);
            h[4]=__float2half_rn(v1.x); h[5]=__float2half_rn(v1.y);
            h[6]=__float2half_rn(v1.z); h[7]=__float2half_rn(v1.w);
        } else {
#pragma unroll
            for (int q = 0; q < 8; q++) h[q] = __half(0.f);
        }
        *(uint4*)(d_Wd + (size_t)r * HDIM + c) = *(uint4*)h;
    }
}

// ---------------- router (inline threefry gumbel; fp32 partials, double reduce) ----------------
__global__ void router_kernel(const float* __restrict__ x,
                              const float* __restrict__ rw,
                              const float* __restrict__ rb) {
    int gw = (blockIdx.x * blockDim.x + threadIdx.x) >> 5;
    int lane = threadIdx.x & 31;
    if (gw >= NTOK) return;

    // lanes 0..7 each compute the gumbel for expert = lane (JAX threefry2x32, key (0,42))
    float gum = 0.0f;
    if (lane < NEXP) {
        unsigned i = (unsigned)gw * NEXP + lane;
        const uint32_t ks0 = 0u, ks1 = 42u, ks2 = 0u ^ 42u ^ 0x1BD11BDAu;
        uint32_t x0 = 0u + ks0;
        uint32_t x1 = i  + ks1;
#define TF_RND(r) { x0 += x1; x1 = (x1 << (r)) | (x1 >> (32 - (r))); x1 ^= x0; }
        TF_RND(13) TF_RND(15) TF_RND(26) TF_RND(6)   x0 += ks1; x1 += ks2 + 1u;
        TF_RND(17) TF_RND(29) TF_RND(16) TF_RND(24)  x0 += ks2; x1 += ks0 + 2u;
        TF_RND(13) TF_RND(15) TF_RND(26) TF_RND(6)   x0 += ks0; x1 += ks1 + 3u;
        TF_RND(17) TF_RND(29) TF_RND(16) TF_RND(24)  x0 += ks1; x1 += ks2 + 4u;
        TF_RND(13) TF_RND(15) TF_RND(26) TF_RND(6)   x0 += ks2; x1 += ks0 + 5u;
#undef TF_RND
        uint32_t bits = x0 ^ x1;
        float u = __uint_as_float((bits >> 9) | 0x3F800000u) - 1.0f;
        gum = -logf(-logf(u + 1e-10f) + 1e-10f);
    }

    const float* xr = x + (size_t)gw * HDIM;
    float acc[NEXP];
#pragma unroll
    for (int e = 0; e < NEXP; e++) acc[e] = 0.0f;
    for (int h = lane; h < HDIM; h += 32) {
        float xv = xr[h];
        const float4* w4 = (const float4*)(rw + (size_t)h * NEXP);
        float4 w0 = w4[0], w1 = w4[1];
        acc[0] += xv * w0.x; acc[1] += xv * w0.y;
        acc[2] += xv * w0.z; acc[3] += xv * w0.w;
        acc[4] += xv * w1.x; acc[5] += xv * w1.y;
        acc[6] += xv * w1.z; acc[7] += xv * w1.w;
    }
    double da[NEXP];
#pragma unroll
    for (int e = 0; e < NEXP; e++) da[e] = (double)acc[e];
#pragma unroll
    for (int off = 16; off; off >>= 1)
#pragma unroll
        for (int e = 0; e < NEXP; e++)
            da[e] += __shfl_xor_sync(0xffffffffu, da[e], off);
    float gv[NEXP];
#pragma unroll
    for (int e = 0; e < NEXP; e++) gv[e] = __shfl_sync(0xffffffffu, gum, e);
    if (lane == 0) {
        float hh[NEXP]; float mx = -1e30f;
#pragma unroll
        for (int e = 0; e < NEXP; e++) {
            hh[e] = (float)da[e] + rb[e] + gv[e];
            mx = fmaxf(mx, hh[e]);
        }
        float s = 0.0f;
#pragma unroll
        for (int e = 0; e < NEXP; e++) { hh[e] = expf(hh[e] - mx); s += hh[e]; }
        float inv = 1.0f / s;
#pragma unroll
        for (int e = 0; e < NEXP; e++) d_Sm[(size_t)e * NTOK + gw] = hh[e] * inv;
    }
}

// ---------------- rank-select top-k ----------------
__global__ void __launch_bounds__(1024) rank_topk_kernel() {
    __shared__ float sval[NTOK];
    int e = blockIdx.x >> 3;
    int chunk = blockIdx.x & 7;
    int tid = threadIdx.x;
    const float* Se = d_Sm + (size_t)e * NTOK;
    for (int i = tid; i < NTOK; i += 1024) sval[i] = Se[i];
    __syncthreads();
    int t = chunk * 1024 + tid;
    float v = sval[t];
    int rank = 0;
#pragma unroll 8
    for (int j = 0; j < NTOK; j++) {
        float vj = sval[j];
        rank += (vj > v) || (vj == v && j < t);
    }
    if (rank < KCAP) {
        int pos = atomicAdd(&d_cnt[e], 1);
        d_idx[e * KCAP + pos] = t;
        d_G[e * KCAP + pos]   = v;
    }
}

// ---------------- gather routed tokens -> fp16 ----------------
__global__ void gather_kernel(const float* __restrict__ x) {
    int r = blockIdx.x;
    int tok = d_idx[r];
    const float4* src = (const float4*)(x + (size_t)tok * HDIM);
    __half2* dst = (__half2*)(d_Xg + (size_t)r * HDIM);
    for (int i = threadIdx.x; i < HDIM / 4; i += blockDim.x) {
        float4 v = src[i];
        dst[i * 2]     = __floats2half2_rn(v.x, v.y);
        dst[i * 2 + 1] = __floats2half2_rn(v.z, v.w);
    }
}

// =============== fused GEMM1+2: Xg*[Wg|Wu] -> silu -> d_Hh ===============
// CTA 128(M) x 64(N), two B tensors. BK=64, NS=3, 256 thr (8 warps: 4M x 2N),
// warp tile 32x32 per output tensor. Loads for stage i+2 interleaved between
// the four ks compute blocks.
#define F_AB   16384                 // A 128x64 half
#define F_BB   8192                  // each B 64x64 half
#define F_STG  (F_AB + 2 * F_BB)     // 32768
#define NS     3
#define DYN    (NS * F_STG)          // 98304

__device__ __forceinline__ void loadA12(uint32_t st, const __half* Asrc, int tid) {
#pragma unroll
    for (int t = 0; t < 4; t++) {        // A: 128 rows x 8 chunks
        int idx = tid + t * 256;
        int m = idx >> 3, kc = idx & 7;
        uint32_t dst = st + (uint32_t)(m * 128) + (uint32_t)((kc << 4) ^ ((m & 7) << 4));
        cpasync16(dst, Asrc + (size_t)m * HDIM + kc * 8);
    }
}
__device__ __forceinline__ void loadB12(uint32_t st, const __half* Bsrc, int tid) {
#pragma unroll
    for (int t = 0; t < 2; t++) {        // B: 64 rows x 8 chunks
        int idx = tid + t * 256;
        int k = idx >> 3, nc = idx & 7;
        uint32_t dst = st + (uint32_t)(k * 128) + (uint32_t)((nc << 4) ^ ((k & 7) << 4));
        cpasync16(dst, Bsrc + (size_t)k * NPAD + nc * 8);
    }
}

__global__ void __launch_bounds__(256) gemm_fused12(
    const float* __restrict__ bg, const float* __restrict__ bu)
{
    extern __shared__ __align__(1024) char dsm[];
    uint32_t sbase = smem_u32(dsm);
    int tid = threadIdx.x, wid = tid >> 5, lane = tid & 31;
    int gp = lane >> 2, tg = lane & 3;
    int wm = (wid >> 1) * 32;            // 4 warp rows
    int wn = (wid & 1) * 32;             // 2 warp cols
    int bm = blockIdx.y * 128, bn = blockIdx.x * 64;

    const __half* Ag = d_Xg + (size_t)bm * HDIM;
    const __half* Bg = d_Wg + bn;
    const __half* Bu = d_Wu + bn;
    const int NC = HDIM >> 6;            // 32

    float cg[2][4][4], cu[2][4][4];
#pragma unroll
    for (int mi = 0; mi < 2; mi++)
#pragma unroll
        for (int ni = 0; ni < 4; ni++)
#pragma unroll
            for (int q = 0; q < 4; q++) { cg[mi][ni][q] = 0.f; cu[mi][ni][q] = 0.f; }

#pragma unroll
    for (int p = 0; p < 2; p++) {
        uint32_t st = sbase + p * F_STG;
        loadA12(st, Ag + p * 64, tid);
        loadB12(st + F_AB,        Bg + (size_t)(p * 64) * NPAD, tid);
        loadB12(st + F_AB + F_BB, Bu + (size_t)(p * 64) * NPAD, tid);
        CP_COMMIT();
    }

    int mat = lane >> 3, r8 = lane & 7;

    for (int i = 0; i < NC; i++) {
        CP_WAIT1();
        __syncthreads();

        uint32_t abase = sbase + (i % NS) * F_STG;
        uint32_t gbase = abase + F_AB;
        uint32_t ubase = gbase + F_BB;

        bool more = (i + 2 < NC);
        int i2 = more ? (i + 2) : 0;
        uint32_t nst = sbase + (i2 % NS) * F_STG;

#define KS12(kk) do {                                                              \
        uint32_t a_[2][4], bG_[4][2], bU_[4][2];                                   \
        _Pragma("unroll")                                                          \
        for (int mi = 0; mi < 2; mi++) {                                           \
            int m = wm + mi * 16 + r8 + (mat & 1) * 8;                             \
            int kc = ((kk) >> 3) + (mat >> 1);                                     \
            uint32_t addr = abase + (uint32_t)(m * 128)                            \
                          + (uint32_t)((kc << 4) ^ ((m & 7) << 4));                \
            ldm_x4(a_[mi], addr);                                                  \
        }                                                                          \
        int kq = (kk) + (mat & 1) * 8 + r8;                                        \
        _Pragma("unroll")                                                          \
        for (int nj = 0; nj < 2; nj++) {                                           \
            int n = wn + nj * 16 + (mat >> 1) * 8;                                 \
            uint32_t off = (uint32_t)(kq * 128)                                    \
                         + (uint32_t)((((n >> 3) & 7) << 4) ^ ((kq & 7) << 4));    \
            uint32_t t4[4];                                                        \
            ldm_x4_t(t4, gbase + off);                                             \
            bG_[nj*2+0][0] = t4[0]; bG_[nj*2+0][1] = t4[1];                        \
            bG_[nj*2+1][0] = t4[2]; bG_[nj*2+1][1] = t4[3];                        \
            ldm_x4_t(t4, ubase + off);                                             \
            bU_[nj*2+0][0] = t4[0]; bU_[nj*2+0][1] = t4[1];                        \
            bU_[nj*2+1][0] = t4[2]; bU_[nj*2+1][1] = t4[3];                        \
        }                                                                          \
        _Pragma("unroll")                                                          \
        for (int mi = 0; mi < 2; mi++)                                             \
            _Pragma("unroll")                                                      \
            for (int ni = 0; ni < 4; ni++) {                                       \
                mma16816(cg[mi][ni], a_[mi], bG_[ni]);                             \
                mma16816(cu[mi][ni], a_[mi], bU_[ni]);                             \
            }                                                                      \
    } while (0)

        KS12(0);
        if (more) loadA12(nst, Ag + i2 * 64, tid);
        KS12(16);
        if (more) loadB12(nst + F_AB, Bg + (size_t)(i2 * 64) * NPAD, tid);
        KS12(32);
        if (more) loadB12(nst + F_AB + F_BB, Bu + (size_t)(i2 * 64) * NPAD, tid);
        CP_COMMIT();
        KS12(48);
#undef KS12
    }

    // epilogue: silu(gate+bg)*(up+bu) -> d_Hh (pad cols zeroed)
#pragma unroll
    for (int mi = 0; mi < 2; mi++) {
        int row = bm + wm + mi * 16 + gp;
#pragma unroll
        for (int ni = 0; ni < 4; ni++) {
            int col = bn + wn + ni * 8 + 2 * tg;
            float b0g = 0.f, b1g = 0.f, b0u = 0.f, b1u = 0.f;
            bool v0 = col < DFF, v1 = (col + 1) < DFF;
            if (v0) { b0g = bg[col];     b0u = bu[col]; }
            if (v1) { b1g = bg[col + 1]; b1u = bu[col + 1]; }
#pragma unroll
            for (int h = 0; h < 2; h++) {
                int r2 = row + h * 8;
                float o0 = 0.f, o1 = 0.f;
                if (v0) {
                    float gate = cg[mi][ni][h * 2 + 0] + b0g;
                    float up   = cu[mi][ni][h * 2 + 0] + b0u;
                    o0 = gate * (1.0f / (1.0f + expf(-gate))) * up;
                }
                if (v1) {
                    float gate = cg[mi][ni][h * 2 + 1] + b1g;
                    float up   = cu[mi][ni][h * 2 + 1] + b1u;
                    o1 = gate * (1.0f / (1.0f + expf(-gate))) * up;
                }
                *(__half2*)(d_Hh + (size_t)r2 * NPAD + col) = __floats2half2_rn(o0, o1);
            }
        }
    }
}

// =============== GEMM3: Hh * Wd -> atomicAdd(out) ===============
// CTA 128x128, BK=64, NS=3, 256 thr (8 warps: 2M x 4N), warp tile 64x32.
// Loads for stage i+2 interleaved between ks compute blocks.
#define ABYTES 16384            // 128 x 64 half
#define STG3   32768            // + B 64 x 128 half

__device__ __forceinline__ void loadA3(uint32_t st, const __half* Asrc, int tid) {
#pragma unroll
    for (int t = 0; t < 4; t++) {
        int idx = tid + t * 256;
        int m = idx >> 3, kc = idx & 7;
        uint32_t dst = st + (uint32_t)(m * 128) + (uint32_t)((kc << 4) ^ ((m & 7) << 4));
        cpasync16(dst, Asrc + (size_t)m * NPAD + kc * 8);
    }
}
template <int T0>
__device__ __forceinline__ void loadB3(uint32_t st, const __half* Bsrc, int tid) {
#pragma unroll
    for (int t = T0; t < T0 + 2; t++) {
        int idx = tid + t * 256;
        int k = idx >> 4, nc = idx & 15;
        uint32_t dst = st + (uint32_t)ABYTES + (uint32_t)(k * 256) + (uint32_t)((nc & 8) << 4)
                     + (uint32_t)(((nc & 7) << 4) ^ ((k & 7) << 4));
        cpasync16(dst, Bsrc + (size_t)k * HDIM + nc * 8);
    }
}

__global__ void __launch_bounds__(256) gemm3(
    const float* __restrict__ bdn, float* __restrict__ out)
{
    extern __shared__ __align__(1024) char dsm[];
    uint32_t sbase = smem_u32(dsm);
    int tid = threadIdx.x, wid = tid >> 5, lane = tid & 31;
    int gp = lane >> 2, tg = lane & 3;
    int wm = (wid >> 2) * 64;
    int wn = (wid & 3) * 32;
    int bm = blockIdx.y * 128, bn = blockIdx.x * 128;

    const __half* Ag = d_Hh + (size_t)bm * NPAD;
    const __half* Bg = d_Wd + bn;
    const int NC = NPAD >> 6;    // 86

    float c[4][4][4];
#pragma unroll
    for (int mi = 0; mi < 4; mi++)
#pragma unroll
        for (int ni = 0; ni < 4; ni++)
#pragma unroll
            for (int q = 0; q < 4; q++) c[mi][ni][q] = 0.0f;

#pragma unroll
    for (int p = 0; p < 2; p++) {
        uint32_t st = sbase + p * STG3;
        loadA3(st, Ag + p * 64, tid);
        loadB3<0>(st, Bg + (size_t)(p * 64) * HDIM, tid);
        loadB3<2>(st, Bg + (size_t)(p * 64) * HDIM, tid);
        CP_COMMIT();
    }

    int mat = lane >> 3, r8 = lane & 7;

    for (int i = 0; i < NC; i++) {
        CP_WAIT1();
        __syncthreads();

        uint32_t abase = sbase + (i % NS) * STG3;
        uint32_t bbase = abase + ABYTES;

        bool more = (i + 2 < NC);
        int i2 = more ? (i + 2) : 0;
        uint32_t nst = sbase + (i2 % NS) * STG3;
        const __half* Bn = Bg + (size_t)(i2 * 64) * HDIM;

#define KS3(kk) do {                                                               \
        uint32_t a_[4][4], b_[4][2];                                               \
        _Pragma("unroll")                                                          \
        for (int mi = 0; mi < 4; mi++) {                                           \
            int m = wm + mi * 16 + r8 + (mat & 1) * 8;                             \
            int kc = ((kk) >> 3) + (mat >> 1);                                     \
            uint32_t addr = abase + (uint32_t)(m * 128)                            \
                          + (uint32_t)((kc << 4) ^ ((m & 7) << 4));                \
            ldm_x4(a_[mi], addr);                                                  \
        }                                                                          \
        int kq = (kk) + (mat & 1) * 8 + r8;                                        \
        _Pragma("unroll")                                                          \
        for (int nj = 0; nj < 2; nj++) {                                           \
            int n = wn + nj * 16 + (mat >> 1) * 8;                                 \
            uint32_t addr = bbase + (uint32_t)(kq * 256) + (uint32_t)((n & 64) << 1) \
                          + (uint32_t)((((n >> 3) & 7) << 4) ^ ((kq & 7) << 4));   \
            uint32_t t4[4];                                                        \
            ldm_x4_t(t4, addr);                                                    \
            b_[nj*2+0][0] = t4[0]; b_[nj*2+0][1] = t4[1];                          \
            b_[nj*2+1][0] = t4[2]; b_[nj*2+1][1] = t4[3];                          \
        }                                                                          \
        _Pragma("unroll")                                                          \
        for (int mi = 0; mi < 4; mi++)                                             \
            _Pragma("unroll")                                                      \
            for (int ni = 0; ni < 4; ni++)                                         \
                mma16816(c[mi][ni], a_[mi], b_[ni]);                               \
    } while (0)

        KS3(0);
        if (more) loadA3(nst, Ag + i2 * 64, tid);
        KS3(16);
        if (more) loadB3<0>(nst, Bn, tid);
        KS3(32);
        if (more) loadB3<2>(nst, Bn, tid);
        CP_COMMIT();
        KS3(48);
#undef KS3
    }

#pragma unroll
    for (int mi = 0; mi < 4; mi++) {
        int row = bm + wm + mi * 16 + gp;
        int tok0 = d_idx[row];     float g0 = d_G[row];
        int tok1 = d_idx[row + 8]; float g1 = d_G[row + 8];
#pragma unroll
        for (int ni = 0; ni < 4; ni++) {
            int col = bn + wn + ni * 8 + 2 * tg;
            float b0 = bdn[col], b1 = bdn[col + 1];
            float* o0 = out + (size_t)tok0 * HDIM + col;
            atomicAdd(o0,     g0 * (c[mi][ni][0] + b0));
            atomicAdd(o0 + 1, g0 * (c[mi][ni][1] + b1));
            float* o1 = out + (size_t)tok1 * HDIM + col;
            atomicAdd(o1,     g1 * (c[mi][ni][2] + b0));
            atomicAdd(o1 + 1, g1 * (c[mi][ni][3] + b1));
        }
    }
}

// ---------------- launch ----------------
extern "C" void kernel_launch(void* const* d_in, const int* in_sizes, int n_in,
                              void* d_out, int out_size) {
    const float* x  = (const float*)d_in[0];
    const float* rw = (const float*)d_in[1];
    const float* rb = (const float*)d_in[2];
    const float* wg = (const float*)d_in[3];
    const float* bg = (const float*)d_in[4];
    const float* wu = (const float*)d_in[5];
    const float* bu = (const float*)d_in[6];
    const float* wd = (const float*)d_in[7];
    const float* bd = (const float*)d_in[8];
    float* out = (float*)d_out;

    cudaFuncSetAttribute(gemm_fused12, cudaFuncAttributeMaxDynamicSharedMemorySize, DYN);
    cudaFuncSetAttribute(gemm3,        cudaFuncAttributeMaxDynamicSharedMemorySize, DYN);

    size_t n4 = (size_t)out_size / 4;
    zero_kernel<<<(n4 + 255) / 256, 256>>>((float4*)out, n4);

    int t8GU = HDIM * NPAD / 8;
    int t8D  = NPAD * HDIM / 8;
    padconv_kernel<0><<<(t8GU + 255) / 256, 256>>>(wg, t8GU);
    padconv_kernel<1><<<(t8GU + 255) / 256, 256>>>(wu, t8GU);
    padconv_kernel<2><<<(t8D  + 255) / 256, 256>>>(wd, t8D);

    router_kernel<<<NTOK / 8, 256>>>(x, rw, rb);
    rank_topk_kernel<<<64, 1024>>>();
    gather_kernel<<<NSLOT, 256>>>(x);

    dim3 g12(NPAD / 64, NSLOT / 128);    // (86, 64)
    gemm_fused12<<<g12, 256, DYN>>>(bg, bu);

    dim3 g3(HDIM / 128, NSLOT / 128);    // (16, 64)
    gemm3<<<g3, 256, DYN>>>(bd, out);
}

// round 13
// speedup vs baseline: 1.0278x; 1.0278x over previous
#include <cuda_runtime.h>
#include <cuda_fp16.h>
#include <cstdint>
#include <cstddef>

#define NTOK 8192
#define HDIM 2048
#define NEXP 8
#define KCAP 1024
#define DFF  5461
#define NPAD 5504
#define KHALF 2752
#define NSLOT 8192   // NEXP * KCAP

// ---------------- device scratch (static, no allocations) ----------------
__device__ float  d_Sm [NEXP * NTOK];            // transposed: [expert][token]
__device__ int    d_cnt[NEXP];
__device__ int    d_idx[NSLOT];
__device__ float  d_G  [NSLOT];
__device__ __half d_Xg [(size_t)NSLOT * HDIM];   // gathered tokens fp16
__device__ __half d_Wg [(size_t)HDIM * NPAD];    // w_gate  [K=2048][N=5504] fp16
__device__ __half d_Wu [(size_t)HDIM * NPAD];    // w_up
__device__ __half d_Wd [(size_t)NPAD * HDIM];    // w_down  [K=5504][N=2048] fp16
__device__ __half d_Hh [(size_t)NSLOT * NPAD];   // silu(g)*up fp16

// ---------------- helpers ----------------
__device__ __forceinline__ uint32_t smem_u32(const void* p) {
    uint32_t a;
    asm("{ .reg .u64 t; cvta.to.shared.u64 t, %1; cvt.u32.u64 %0, t; }" : "=r"(a) : "l"(p));
    return a;
}
__device__ __forceinline__ void cpasync16(uint32_t dst, const void* src) {
    asm volatile("cp.async.cg.shared.global [%0], [%1], 16;" :: "r"(dst), "l"(src) : "memory");
}
#define CP_COMMIT()  asm volatile("cp.async.commit_group;" ::: "memory")
#define CP_WAIT1()   asm volatile("cp.async.wait_group 1;" ::: "memory")

__device__ __forceinline__ void ldm_x4(uint32_t* r, uint32_t a) {
    asm volatile("ldmatrix.sync.aligned.m8n8.x4.shared.b16 {%0,%1,%2,%3}, [%4];"
                 : "=r"(r[0]), "=r"(r[1]), "=r"(r[2]), "=r"(r[3]) : "r"(a));
}
__device__ __forceinline__ void ldm_x4_t(uint32_t* r, uint32_t a) {
    asm volatile("ldmatrix.sync.aligned.m8n8.x4.trans.shared.b16 {%0,%1,%2,%3}, [%4];"
                 : "=r"(r[0]), "=r"(r[1]), "=r"(r[2]), "=r"(r[3]) : "r"(a));
}
__device__ __forceinline__ void mma16816(float* c, const uint32_t* a, const uint32_t* b) {
    asm volatile(
        "mma.sync.aligned.m16n8k16.row.col.f32.f16.f16.f32 "
        "{%0,%1,%2,%3}, {%4,%5,%6,%7}, {%8,%9}, {%0,%1,%2,%3};"
        : "+f"(c[0]), "+f"(c[1]), "+f"(c[2]), "+f"(c[3])
        : "r"(a[0]), "r"(a[1]), "r"(a[2]), "r"(a[3]), "r"(b[0]), "r"(b[1]));
}

// ---------------- zero output (float4) ----------------
__global__ void zero_kernel(float4* p, size_t n4) {
    size_t i = (size_t)blockIdx.x * blockDim.x + threadIdx.x;
    if (i < n4) p[i] = make_float4(0.f, 0.f, 0.f, 0.f);
}

// ---------------- pad + fp16-convert weights ----------------
// Vectorized stores; scalar source loads for SEL 0/1 (DFF=5461 odd -> float4 misaligned).
template <int SEL>
__global__ void padconv_kernel(const float* __restrict__ src, int total8) {
    int i = blockIdx.x * blockDim.x + threadIdx.x;
    if (SEL == 0 && i < NEXP) d_cnt[i] = 0;
    if (i >= total8) return;
    __half h[8];
    if (SEL < 2) {
        int r = i / (NPAD / 8), c = (i - r * (NPAD / 8)) * 8;
        const float* s = src + (size_t)r * DFF + c;
#pragma unroll
        for (int q = 0; q < 8; q++)
            h[q] = (c + q < DFF) ? __float2half_rn(__ldg(s + q)) : __half(0.f);
        __half* dst = (SEL == 0) ? d_Wg : d_Wu;
        *(uint4*)(dst + (size_t)r * NPAD + c) = *(uint4*)h;
    } else {
        int r = i / (HDIM / 8), c = (i - r * (HDIM / 8)) * 8;
        if (r < DFF) {
            const float* s = src + (size_t)r * HDIM + c;
            float4 v0 = *(const float4*)s, v1 = *(const float4*)(s + 4);
            h[0]=__float2half_rn(v0.x); h[1]=__float2half_rn(v0.y);
            h[2]=__float2half_rn(v0.z); h[3]=__float2half_rn(v0.w);
            h[4]=__float2half_rn(v1.x); h[5]=__float2half_rn(v1.y);
            h[6]=__float2half_rn(v1.z); h[7]=__float2half_rn(v1.w);
        } else {
#pragma unroll
            for (int q = 0; q < 8; q++) h[q] = __half(0.f);
        }
        *(uint4*)(d_Wd + (size_t)r * HDIM + c) = *(uint4*)h;
    }
}

// ---------------- router (inline threefry gumbel; fp32 partials, double reduce) ----------------
__global__ void router_kernel(const float* __restrict__ x,
                              const float* __restrict__ rw,
                              const float* __restrict__ rb) {
    int gw = (blockIdx.x * blockDim.x + threadIdx.x) >> 5;
    int lane = threadIdx.x & 31;
    if (gw >= NTOK) return;

    // lanes 0..7 each compute the gumbel for expert = lane (JAX threefry2x32, key (0,42))
    float gum = 0.0f;
    if (lane < NEXP) {
        unsigned i = (unsigned)gw * NEXP + lane;
        const uint32_t ks0 = 0u, ks1 = 42u, ks2 = 0u ^ 42u ^ 0x1BD11BDAu;
        uint32_t x0 = 0u + ks0;
        uint32_t x1 = i  + ks1;
#define TF_RND(r) { x0 += x1; x1 = (x1 << (r)) | (x1 >> (32 - (r))); x1 ^= x0; }
        TF_RND(13) TF_RND(15) TF_RND(26) TF_RND(6)   x0 += ks1; x1 += ks2 + 1u;
        TF_RND(17) TF_RND(29) TF_RND(16) TF_RND(24)  x0 += ks2; x1 += ks0 + 2u;
        TF_RND(13) TF_RND(15) TF_RND(26) TF_RND(6)   x0 += ks0; x1 += ks1 + 3u;
        TF_RND(17) TF_RND(29) TF_RND(16) TF_RND(24)  x0 += ks1; x1 += ks2 + 4u;
        TF_RND(13) TF_RND(15) TF_RND(26) TF_RND(6)   x0 += ks2; x1 += ks0 + 5u;
#undef TF_RND
        uint32_t bits = x0 ^ x1;
        float u = __uint_as_float((bits >> 9) | 0x3F800000u) - 1.0f;
        gum = -logf(-logf(u + 1e-10f) + 1e-10f);
    }

    const float* xr = x + (size_t)gw * HDIM;
    float acc[NEXP];
#pragma unroll
    for (int e = 0; e < NEXP; e++) acc[e] = 0.0f;
    for (int h = lane; h < HDIM; h += 32) {
        float xv = xr[h];
        const float4* w4 = (const float4*)(rw + (size_t)h * NEXP);
        float4 w0 = w4[0], w1 = w4[1];
        acc[0] += xv * w0.x; acc[1] += xv * w0.y;
        acc[2] += xv * w0.z; acc[3] += xv * w0.w;
        acc[4] += xv * w1.x; acc[5] += xv * w1.y;
        acc[6] += xv * w1.z; acc[7] += xv * w1.w;
    }
    double da[NEXP];
#pragma unroll
    for (int e = 0; e < NEXP; e++) da[e] = (double)acc[e];
#pragma unroll
    for (int off = 16; off; off >>= 1)
#pragma unroll
        for (int e = 0; e < NEXP; e++)
            da[e] += __shfl_xor_sync(0xffffffffu, da[e], off);
    float gv[NEXP];
#pragma unroll
    for (int e = 0; e < NEXP; e++) gv[e] = __shfl_sync(0xffffffffu, gum, e);
    if (lane == 0) {
        float hh[NEXP]; float mx = -1e30f;
#pragma unroll
        for (int e = 0; e < NEXP; e++) {
            hh[e] = (float)da[e] + rb[e] + gv[e];
            mx = fmaxf(mx, hh[e]);
        }
        float s = 0.0f;
#pragma unroll
        for (int e = 0; e < NEXP; e++) { hh[e] = expf(hh[e] - mx); s += hh[e]; }
        float inv = 1.0f / s;
#pragma unroll
        for (int e = 0; e < NEXP; e++) d_Sm[(size_t)e * NTOK + gw] = hh[e] * inv;
    }
}

// ---------------- rank-select top-k ----------------
__global__ void __launch_bounds__(1024) rank_topk_kernel() {
    __shared__ float sval[NTOK];
    int e = blockIdx.x >> 3;
    int chunk = blockIdx.x & 7;
    int tid = threadIdx.x;
    const float* Se = d_Sm + (size_t)e * NTOK;
    for (int i = tid; i < NTOK; i += 1024) sval[i] = Se[i];
    __syncthreads();
    int t = chunk * 1024 + tid;
    float v = sval[t];
    int rank = 0;
#pragma unroll 8
    for (int j = 0; j < NTOK; j++) {
        float vj = sval[j];
        rank += (vj > v) || (vj == v && j < t);
    }
    if (rank < KCAP) {
        int pos = atomicAdd(&d_cnt[e], 1);
        d_idx[e * KCAP + pos] = t;
        d_G[e * KCAP + pos]   = v;
    }
}

// ---------------- gather routed tokens -> fp16 ----------------
__global__ void gather_kernel(const float* __restrict__ x) {
    int r = blockIdx.x;
    int tok = d_idx[r];
    const float4* src = (const float4*)(x + (size_t)tok * HDIM);
    __half2* dst = (__half2*)(d_Xg + (size_t)r * HDIM);
    for (int i = threadIdx.x; i < HDIM / 4; i += blockDim.x) {
        float4 v = src[i];
        dst[i * 2]     = __floats2half2_rn(v.x, v.y);
        dst[i * 2 + 1] = __floats2half2_rn(v.z, v.w);
    }
}

// =============== fused GEMM1+2: Xg*[Wg|Wu] -> silu -> d_Hh (round-9 body) ===============
// CTA 128(M) x 64(N), two B tensors. BK=64, NS=3, 256 thr (8 warps: 4M x 2N),
// warp tile 32x32 per output tensor.
#define F_AB   16384                 // A 128x64 half
#define F_BB   8192                  // each B 64x64 half
#define F_STG  (F_AB + 2 * F_BB)     // 32768
#define NS     3
#define DYN    (NS * F_STG)          // 98304

__device__ __forceinline__ void load_stage12(uint32_t st, const __half* Ag,
                                             const __half* Bg, const __half* Bu,
                                             int i, int tid) {
    const __half* Asrc = Ag + i * 64;
    const __half* Bgs = Bg + (size_t)(i * 64) * NPAD;
    const __half* Bus = Bu + (size_t)(i * 64) * NPAD;
#pragma unroll
    for (int t = 0; t < 4; t++) {        // A: 128 rows x 8 chunks
        int idx = tid + t * 256;
        int m = idx >> 3, kc = idx & 7;
        uint32_t dst = st + (uint32_t)(m * 128) + (uint32_t)((kc << 4) ^ ((m & 7) << 4));
        cpasync16(dst, Asrc + (size_t)m * HDIM + kc * 8);
    }
#pragma unroll
    for (int t = 0; t < 2; t++) {        // Bg
        int idx = tid + t * 256;
        int k = idx >> 3, nc = idx & 7;
        uint32_t dst = st + F_AB + (uint32_t)(k * 128) + (uint32_t)((nc << 4) ^ ((k & 7) << 4));
        cpasync16(dst, Bgs + (size_t)k * NPAD + nc * 8);
    }
#pragma unroll
    for (int t = 0; t < 2; t++) {        // Bu
        int idx = tid + t * 256;
        int k = idx >> 3, nc = idx & 7;
        uint32_t dst = st + F_AB + F_BB + (uint32_t)(k * 128) + (uint32_t)((nc << 4) ^ ((k & 7) << 4));
        cpasync16(dst, Bus + (size_t)k * NPAD + nc * 8);
    }
}

__global__ void __launch_bounds__(256) gemm_fused12(
    const float* __restrict__ bg, const float* __restrict__ bu)
{
    extern __shared__ __align__(1024) char dsm[];
    uint32_t sbase = smem_u32(dsm);
    int tid = threadIdx.x, wid = tid >> 5, lane = tid & 31;
    int gp = lane >> 2, tg = lane & 3;
    int wm = (wid >> 1) * 32;            // 4 warp rows
    int wn = (wid & 1) * 32;             // 2 warp cols
    int bm = blockIdx.y * 128, bn = blockIdx.x * 64;

    const __half* Ag = d_Xg + (size_t)bm * HDIM;
    const __half* Bg = d_Wg + bn;
    const __half* Bu = d_Wu + bn;
    const int NC = HDIM >> 6;            // 32

    float cg[2][4][4], cu[2][4][4];
#pragma unroll
    for (int mi = 0; mi < 2; mi++)
#pragma unroll
        for (int ni = 0; ni < 4; ni++)
#pragma unroll
            for (int q = 0; q < 4; q++) { cg[mi][ni][q] = 0.f; cu[mi][ni][q] = 0.f; }

    load_stage12(sbase,         Ag, Bg, Bu, 0, tid); CP_COMMIT();
    load_stage12(sbase + F_STG, Ag, Bg, Bu, 1, tid); CP_COMMIT();

    int mat = lane >> 3, r8 = lane & 7;

    for (int i = 0; i < NC; i++) {
        CP_WAIT1();
        __syncthreads();
        if (i + 2 < NC) load_stage12(sbase + ((i + 2) % NS) * F_STG, Ag, Bg, Bu, i + 2, tid);
        CP_COMMIT();

        uint32_t abase = sbase + (i % NS) * F_STG;
        uint32_t gbase = abase + F_AB;
        uint32_t ubase = gbase + F_BB;

#pragma unroll
        for (int ks = 0; ks < 4; ks++) {
            int kk = ks * 16;
            uint32_t a[2][4], bG[4][2], bU[4][2];
#pragma unroll
            for (int mi = 0; mi < 2; mi++) {
                int m = wm + mi * 16 + r8 + (mat & 1) * 8;
                int kc = (kk >> 3) + (mat >> 1);
                uint32_t addr = abase + (uint32_t)(m * 128) + (uint32_t)((kc << 4) ^ ((m & 7) << 4));
                ldm_x4(a[mi], addr);
            }
            int kq = kk + (mat & 1) * 8 + r8;
#pragma unroll
            for (int nj = 0; nj < 2; nj++) {
                int n = wn + nj * 16 + (mat >> 1) * 8;
                uint32_t off = (uint32_t)(kq * 128) + (uint32_t)((((n >> 3) & 7) << 4) ^ ((kq & 7) << 4));
                uint32_t t4[4];
                ldm_x4_t(t4, gbase + off);
                bG[nj * 2 + 0][0] = t4[0]; bG[nj * 2 + 0][1] = t4[1];
                bG[nj * 2 + 1][0] = t4[2]; bG[nj * 2 + 1][1] = t4[3];
                ldm_x4_t(t4, ubase + off);
                bU[nj * 2 + 0][0] = t4[0]; bU[nj * 2 + 0][1] = t4[1];
                bU[nj * 2 + 1][0] = t4[2]; bU[nj * 2 + 1][1] = t4[3];
            }
#pragma unroll
            for (int mi = 0; mi < 2; mi++)
#pragma unroll
                for (int ni = 0; ni < 4; ni++) {
                    mma16816(cg[mi][ni], a[mi], bG[ni]);
                    mma16816(cu[mi][ni], a[mi], bU[ni]);
                }
        }
    }

    // epilogue: silu(gate+bg)*(up+bu) -> d_Hh (pad cols zeroed)
#pragma unroll
    for (int mi = 0; mi < 2; mi++) {
        int row = bm + wm + mi * 16 + gp;
#pragma unroll
        for (int ni = 0; ni < 4; ni++) {
            int col = bn + wn + ni * 8 + 2 * tg;
            float b0g = 0.f, b1g = 0.f, b0u = 0.f, b1u = 0.f;
            bool v0 = col < DFF, v1 = (col + 1) < DFF;
            if (v0) { b0g = bg[col];     b0u = bu[col]; }
            if (v1) { b1g = bg[col + 1]; b1u = bu[col + 1]; }
#pragma unroll
            for (int h = 0; h < 2; h++) {
                int r2 = row + h * 8;
                float o0 = 0.f, o1 = 0.f;
                if (v0) {
                    float gate = cg[mi][ni][h * 2 + 0] + b0g;
                    float up   = cu[mi][ni][h * 2 + 0] + b0u;
                    o0 = gate * (1.0f / (1.0f + expf(-gate))) * up;
                }
                if (v1) {
                    float gate = cg[mi][ni][h * 2 + 1] + b1g;
                    float up   = cu[mi][ni][h * 2 + 1] + b1u;
                    o1 = gate * (1.0f / (1.0f + expf(-gate))) * up;
                }
                *(__half2*)(d_Hh + (size_t)r2 * NPAD + col) = __floats2half2_rn(o0, o1);
            }
        }
    }
}

// =============== GEMM3: Hh * Wd -> atomicAdd(out), SPLIT-K2 ===============
// CTA 128x128, BK=64, NS=3, 256 thr (8 warps: 2M x 4N), warp tile 64x32.
// blockIdx.z in {0,1}: each half accumulates K range [kz*2752, kz*2752+2752).
// Bias added only by kz==0.
#define ABYTES 16384            // 128 x 64 half
#define STG3   32768            // + B 64 x 128 half

__device__ __forceinline__ void load_stage3(uint32_t st, const __half* Ag,
                                            const __half* Bg, int i, int tid) {
    const __half* Asrc = Ag + i * 64;
    const __half* Bsrc = Bg + (size_t)(i * 64) * HDIM;
#pragma unroll
    for (int t = 0; t < 4; t++) {
        int idx = tid + t * 256;
        int m = idx >> 3, kc = idx & 7;
        uint32_t dst = st + (uint32_t)(m * 128) + (uint32_t)((kc << 4) ^ ((m & 7) << 4));
        cpasync16(dst, Asrc + (size_t)m * NPAD + kc * 8);
    }
#pragma unroll
    for (int t = 0; t < 4; t++) {
        int idx = tid + t * 256;
        int k = idx >> 4, nc = idx & 15;
        uint32_t dst = st + (uint32_t)ABYTES + (uint32_t)(k * 256) + (uint32_t)((nc & 8) << 4)
                     + (uint32_t)(((nc & 7) << 4) ^ ((k & 7) << 4));
        cpasync16(dst, Bsrc + (size_t)k * HDIM + nc * 8);
    }
}

__global__ void __launch_bounds__(256) gemm3(
    const float* __restrict__ bdn, float* __restrict__ out)
{
    extern __shared__ __align__(1024) char dsm[];
    uint32_t sbase = smem_u32(dsm);
    int tid = threadIdx.x, wid = tid >> 5, lane = tid & 31;
    int gp = lane >> 2, tg = lane & 3;
    int wm = (wid >> 2) * 64;
    int wn = (wid & 3) * 32;
    int bm = blockIdx.y * 128, bn = blockIdx.x * 128;
    int kz = blockIdx.z;

    const __half* Ag = d_Hh + (size_t)bm * NPAD + (size_t)kz * KHALF;
    const __half* Bg = d_Wd + (size_t)kz * KHALF * HDIM + bn;
    const int NC = KHALF >> 6;   // 43

    float c[4][4][4];
#pragma unroll
    for (int mi = 0; mi < 4; mi++)
#pragma unroll
        for (int ni = 0; ni < 4; ni++)
#pragma unroll
            for (int q = 0; q < 4; q++) c[mi][ni][q] = 0.0f;

    load_stage3(sbase,        Ag, Bg, 0, tid); CP_COMMIT();
    load_stage3(sbase + STG3, Ag, Bg, 1, tid); CP_COMMIT();

    int mat = lane >> 3, r8 = lane & 7;

    for (int i = 0; i < NC; i++) {
        CP_WAIT1();
        __syncthreads();
        if (i + 2 < NC) load_stage3(sbase + ((i + 2) % NS) * STG3, Ag, Bg, i + 2, tid);
        CP_COMMIT();

        uint32_t abase = sbase + (i % NS) * STG3;
        uint32_t bbase = abase + ABYTES;

#pragma unroll
        for (int ks = 0; ks < 4; ks++) {
            int kk = ks * 16;
            uint32_t a[4][4], b[4][2];
#pragma unroll
            for (int mi = 0; mi < 4; mi++) {
                int m = wm + mi * 16 + r8 + (mat & 1) * 8;
                int kc = (kk >> 3) + (mat >> 1);
                uint32_t addr = abase + (uint32_t)(m * 128) + (uint32_t)((kc << 4) ^ ((m & 7) << 4));
                ldm_x4(a[mi], addr);
            }
#pragma unroll
            for (int nj = 0; nj < 2; nj++) {
                int kq = kk + (mat & 1) * 8 + r8;
                int n  = wn + nj * 16 + (mat >> 1) * 8;
                uint32_t addr = bbase + (uint32_t)(kq * 256) + (uint32_t)((n & 64) << 1)
                              + (uint32_t)(((((n >> 3) & 7) << 4)) ^ ((kq & 7) << 4));
                uint32_t t4[4];
                ldm_x4_t(t4, addr);
                b[nj * 2 + 0][0] = t4[0]; b[nj * 2 + 0][1] = t4[1];
                b[nj * 2 + 1][0] = t4[2]; b[nj * 2 + 1][1] = t4[3];
            }
#pragma unroll
            for (int mi = 0; mi < 4; mi++)
#pragma unroll
                for (int ni = 0; ni < 4; ni++)
                    mma16816(c[mi][ni], a[mi], b[ni]);
        }
    }

#pragma unroll
    for (int mi = 0; mi < 4; mi++) {
        int row = bm + wm + mi * 16 + gp;
        int tok0 = d_idx[row];     float g0 = d_G[row];
        int tok1 = d_idx[row + 8]; float g1 = d_G[row + 8];
#pragma unroll
        for (int ni = 0; ni < 4; ni++) {
            int col = bn + wn + ni * 8 + 2 * tg;
            float b0 = (kz == 0) ? bdn[col]     : 0.f;
            float b1 = (kz == 0) ? bdn[col + 1] : 0.f;
            float* o0 = out + (size_t)tok0 * HDIM + col;
            atomicAdd(o0,     g0 * (c[mi][ni][0] + b0));
            atomicAdd(o0 + 1, g0 * (c[mi][ni][1] + b1));
            float* o1 = out + (size_t)tok1 * HDIM + col;
            atomicAdd(o1,     g1 * (c[mi][ni][2] + b0));
            atomicAdd(o1 + 1, g1 * (c[mi][ni][3] + b1));
        }
    }
}

// ---------------- launch ----------------
extern "C" void kernel_launch(void* const* d_in, const int* in_sizes, int n_in,
                              void* d_out, int out_size) {
    const float* x  = (const float*)d_in[0];
    const float* rw = (const float*)d_in[1];
    const float* rb = (const float*)d_in[2];
    const float* wg = (const float*)d_in[3];
    const float* bg = (const float*)d_in[4];
    const float* wu = (const float*)d_in[5];
    const float* bu = (const float*)d_in[6];
    const float* wd = (const float*)d_in[7];
    const float* bd = (const float*)d_in[8];
    float* out = (float*)d_out;

    cudaFuncSetAttribute(gemm_fused12, cudaFuncAttributeMaxDynamicSharedMemorySize, DYN);
    cudaFuncSetAttribute(gemm3,        cudaFuncAttributeMaxDynamicSharedMemorySize, DYN);

    size_t n4 = (size_t)out_size / 4;
    zero_kernel<<<(n4 + 255) / 256, 256>>>((float4*)out, n4);

    int t8GU = HDIM * NPAD / 8;
    int t8D  = NPAD * HDIM / 8;
    padconv_kernel<0><<<(t8GU + 255) / 256, 256>>>(wg, t8GU);
    padconv_kernel<1><<<(t8GU + 255) / 256, 256>>>(wu, t8GU);
    padconv_kernel<2><<<(t8D  + 255) / 256, 256>>>(wd, t8D);

    router_kernel<<<NTOK / 8, 256>>>(x, rw, rb);
    rank_topk_kernel<<<64, 1024>>>();
    gather_kernel<<<NSLOT, 256>>>(x);

    dim3 g12(NPAD / 64, NSLOT / 128);        // (86, 64)
    gemm_fused12<<<g12, 256, DYN>>>(bg, bu);

    dim3 g3(HDIM / 128, NSLOT / 128, 2);     // (16, 64, 2) split-K2
    gemm3<<<g3, 256, DYN>>>(bd, out);
}

// round 14
// speedup vs baseline: 1.0438x; 1.0156x over previous
#include <cuda_runtime.h>
#include <cuda_fp16.h>
#include <cstdint>
#include <cstddef>

#define NTOK 8192
#define HDIM 2048
#define NEXP 8
#define KCAP 1024
#define DFF  5461
#define NPAD 5504
#define NSLOT 8192   // NEXP * KCAP

// ---------------- device scratch (static, no allocations) ----------------
__device__ float  d_Sm [NEXP * NTOK];            // transposed: [expert][token]
__device__ int    d_cnt[NEXP];
__device__ int    d_idx[NSLOT];
__device__ float  d_G  [NSLOT];
__device__ __half d_Xg [(size_t)NSLOT * HDIM];   // gathered tokens fp16
__device__ __half d_Wg [(size_t)HDIM * NPAD];    // w_gate  [K=2048][N=5504] fp16
__device__ __half d_Wu [(size_t)HDIM * NPAD];    // w_up
__device__ __half d_Wd [(size_t)NPAD * HDIM];    // w_down  [K=5504][N=2048] fp16
__device__ __half d_Hh [(size_t)NSLOT * NPAD];   // silu(g)*up fp16

// ---------------- helpers ----------------
__device__ __forceinline__ uint32_t smem_u32(const void* p) {
    uint32_t a;
    asm("{ .reg .u64 t; cvta.to.shared.u64 t, %1; cvt.u32.u64 %0, t; }" : "=r"(a) : "l"(p));
    return a;
}
__device__ __forceinline__ void cpasync16(uint32_t dst, const void* src) {
    asm volatile("cp.async.cg.shared.global [%0], [%1], 16;" :: "r"(dst), "l"(src) : "memory");
}
#define CP_COMMIT()  asm volatile("cp.async.commit_group;" ::: "memory")
#define CP_WAIT1()   asm volatile("cp.async.wait_group 1;" ::: "memory")

__device__ __forceinline__ void ldm_x4(uint32_t* r, uint32_t a) {
    asm volatile("ldmatrix.sync.aligned.m8n8.x4.shared.b16 {%0,%1,%2,%3}, [%4];"
                 : "=r"(r[0]), "=r"(r[1]), "=r"(r[2]), "=r"(r[3]) : "r"(a));
}
__device__ __forceinline__ void ldm_x4_t(uint32_t* r, uint32_t a) {
    asm volatile("ldmatrix.sync.aligned.m8n8.x4.trans.shared.b16 {%0,%1,%2,%3}, [%4];"
                 : "=r"(r[0]), "=r"(r[1]), "=r"(r[2]), "=r"(r[3]) : "r"(a));
}
__device__ __forceinline__ void mma16816(float* c, const uint32_t* a, const uint32_t* b) {
    asm volatile(
        "mma.sync.aligned.m16n8k16.row.col.f32.f16.f16.f32 "
        "{%0,%1,%2,%3}, {%4,%5,%6,%7}, {%8,%9}, {%0,%1,%2,%3};"
        : "+f"(c[0]), "+f"(c[1]), "+f"(c[2]), "+f"(c[3])
        : "r"(a[0]), "r"(a[1]), "r"(a[2]), "r"(a[3]), "r"(b[0]), "r"(b[1]));
}

// ================= fused prologue megakernel =================
// One launch covers: router (+inline gumbel), zero(out), padconv x3.
// Section sizes (blocks of 256 threads, all exact multiples -> no bounds checks):
#define NB_R 1024                        // router: 8 tokens per block
#define NB_Z (NTOK * HDIM / 4 / 256)     // 16384 float4 zero blocks
#define NB_W (HDIM * NPAD / 8 / 256)     // 5504 blocks per weight tensor
#define NB_TOTAL (NB_R + NB_Z + 3 * NB_W)

__global__ void __launch_bounds__(256) prologue_kernel(
    const float* __restrict__ x,  const float* __restrict__ rw,
    const float* __restrict__ rb, const float* __restrict__ wg,
    const float* __restrict__ wu, const float* __restrict__ wd,
    float* __restrict__ out)
{
    int b = blockIdx.x;
    int tid = threadIdx.x;

    if (b < NB_R) {
        // ---------- router section ----------
        if (b == 0 && tid < NEXP) d_cnt[tid] = 0;
        int gw = b * 8 + (tid >> 5);
        int lane = tid & 31;

        // lanes 0..7: gumbel for expert = lane (JAX threefry2x32, key (0,42))
        float gum = 0.0f;
        if (lane < NEXP) {
            unsigned i = (unsigned)gw * NEXP + lane;
            const uint32_t ks0 = 0u, ks1 = 42u, ks2 = 0u ^ 42u ^ 0x1BD11BDAu;
            uint32_t x0 = 0u + ks0;
            uint32_t x1 = i  + ks1;
#define TF_RND(r) { x0 += x1; x1 = (x1 << (r)) | (x1 >> (32 - (r))); x1 ^= x0; }
            TF_RND(13) TF_RND(15) TF_RND(26) TF_RND(6)   x0 += ks1; x1 += ks2 + 1u;
            TF_RND(17) TF_RND(29) TF_RND(16) TF_RND(24)  x0 += ks2; x1 += ks0 + 2u;
            TF_RND(13) TF_RND(15) TF_RND(26) TF_RND(6)   x0 += ks0; x1 += ks1 + 3u;
            TF_RND(17) TF_RND(29) TF_RND(16) TF_RND(24)  x0 += ks1; x1 += ks2 + 4u;
            TF_RND(13) TF_RND(15) TF_RND(26) TF_RND(6)   x0 += ks2; x1 += ks0 + 5u;
#undef TF_RND
            uint32_t bits = x0 ^ x1;
            float u = __uint_as_float((bits >> 9) | 0x3F800000u) - 1.0f;
            gum = -logf(-logf(u + 1e-10f) + 1e-10f);
        }

        const float* xr = x + (size_t)gw * HDIM;
        float acc[NEXP];
#pragma unroll
        for (int e = 0; e < NEXP; e++) acc[e] = 0.0f;
        for (int h = lane; h < HDIM; h += 32) {
            float xv = xr[h];
            const float4* w4 = (const float4*)(rw + (size_t)h * NEXP);
            float4 w0 = w4[0], w1 = w4[1];
            acc[0] += xv * w0.x; acc[1] += xv * w0.y;
            acc[2] += xv * w0.z; acc[3] += xv * w0.w;
            acc[4] += xv * w1.x; acc[5] += xv * w1.y;
            acc[6] += xv * w1.z; acc[7] += xv * w1.w;
        }
        double da[NEXP];
#pragma unroll
        for (int e = 0; e < NEXP; e++) da[e] = (double)acc[e];
#pragma unroll
        for (int off = 16; off; off >>= 1)
#pragma unroll
            for (int e = 0; e < NEXP; e++)
                da[e] += __shfl_xor_sync(0xffffffffu, da[e], off);
        float gv[NEXP];
#pragma unroll
        for (int e = 0; e < NEXP; e++) gv[e] = __shfl_sync(0xffffffffu, gum, e);
        if (lane == 0) {
            float hh[NEXP]; float mx = -1e30f;
#pragma unroll
            for (int e = 0; e < NEXP; e++) {
                hh[e] = (float)da[e] + rb[e] + gv[e];
                mx = fmaxf(mx, hh[e]);
            }
            float s = 0.0f;
#pragma unroll
            for (int e = 0; e < NEXP; e++) { hh[e] = expf(hh[e] - mx); s += hh[e]; }
            float inv = 1.0f / s;
#pragma unroll
            for (int e = 0; e < NEXP; e++) d_Sm[(size_t)e * NTOK + gw] = hh[e] * inv;
        }
        return;
    }
    b -= NB_R;

    if (b < NB_Z) {
        // ---------- zero(out) section ----------
        size_t i = (size_t)b * 256 + tid;
        ((float4*)out)[i] = make_float4(0.f, 0.f, 0.f, 0.f);
        return;
    }
    b -= NB_Z;

    if (b < 2 * NB_W) {
        // ---------- padconv wg / wu ([HDIM][DFF] -> [HDIM][NPAD]) ----------
        const float* src = (b < NB_W) ? wg : wu;
        __half* dst = (b < NB_W) ? d_Wg : d_Wu;
        int i = (b % NB_W) * 256 + tid;
        int r = i / (NPAD / 8), c = (i - r * (NPAD / 8)) * 8;
        const float* s = src + (size_t)r * DFF + c;
        __half h[8];
#pragma unroll
        for (int q = 0; q < 8; q++)
            h[q] = (c + q < DFF) ? __float2half_rn(__ldg(s + q)) : __half(0.f);
        *(uint4*)(dst + (size_t)r * NPAD + c) = *(uint4*)h;
        return;
    }
    b -= 2 * NB_W;

    {
        // ---------- padconv wd ([DFF][HDIM] -> [NPAD][HDIM]) ----------
        int i = b * 256 + tid;
        int r = i / (HDIM / 8), c = (i - r * (HDIM / 8)) * 8;
        __half h[8];
        if (r < DFF) {
            const float* s = wd + (size_t)r * HDIM + c;
            float4 v0 = *(const float4*)s, v1 = *(const float4*)(s + 4);
            h[0]=__float2half_rn(v0.x); h[1]=__float2half_rn(v0.y);
            h[2]=__float2half_rn(v0.z); h[3]=__float2half_rn(v0.w);
            h[4]=__float2half_rn(v1.x); h[5]=__float2half_rn(v1.y);
            h[6]=__float2half_rn(v1.z); h[7]=__float2half_rn(v1.w);
        } else {
#pragma unroll
            for (int q = 0; q < 8; q++) h[q] = __half(0.f);
        }
        *(uint4*)(d_Wd + (size_t)r * HDIM + c) = *(uint4*)h;
    }
}

// ---------------- rank-select top-k ----------------
__global__ void __launch_bounds__(1024) rank_topk_kernel() {
    __shared__ float sval[NTOK];
    int e = blockIdx.x >> 3;
    int chunk = blockIdx.x & 7;
    int tid = threadIdx.x;
    const float* Se = d_Sm + (size_t)e * NTOK;
    for (int i = tid; i < NTOK; i += 1024) sval[i] = Se[i];
    __syncthreads();
    int t = chunk * 1024 + tid;
    float v = sval[t];
    int rank = 0;
#pragma unroll 8
    for (int j = 0; j < NTOK; j++) {
        float vj = sval[j];
        rank += (vj > v) || (vj == v && j < t);
    }
    if (rank < KCAP) {
        int pos = atomicAdd(&d_cnt[e], 1);
        d_idx[e * KCAP + pos] = t;
        d_G[e * KCAP + pos]   = v;
    }
}

// ---------------- gather routed tokens -> fp16 ----------------
__global__ void gather_kernel(const float* __restrict__ x) {
    int r = blockIdx.x;
    int tok = d_idx[r];
    const float4* src = (const float4*)(x + (size_t)tok * HDIM);
    __half2* dst = (__half2*)(d_Xg + (size_t)r * HDIM);
    for (int i = threadIdx.x; i < HDIM / 4; i += blockDim.x) {
        float4 v = src[i];
        dst[i * 2]     = __floats2half2_rn(v.x, v.y);
        dst[i * 2 + 1] = __floats2half2_rn(v.z, v.w);
    }
}

// =============== fused GEMM1+2: Xg*[Wg|Wu] -> silu -> d_Hh (round-9 body) ===============
// CTA 128(M) x 64(N), two B tensors. BK=64, NS=3, 256 thr (8 warps: 4M x 2N),
// warp tile 32x32 per output tensor.
#define F_AB   16384                 // A 128x64 half
#define F_BB   8192                  // each B 64x64 half
#define F_STG  (F_AB + 2 * F_BB)     // 32768
#define NS     3
#define DYN    (NS * F_STG)          // 98304

__device__ __forceinline__ void load_stage12(uint32_t st, const __half* Ag,
                                             const __half* Bg, const __half* Bu,
                                             int i, int tid) {
    const __half* Asrc = Ag + i * 64;
    const __half* Bgs = Bg + (size_t)(i * 64) * NPAD;
    const __half* Bus = Bu + (size_t)(i * 64) * NPAD;
#pragma unroll
    for (int t = 0; t < 4; t++) {        // A: 128 rows x 8 chunks
        int idx = tid + t * 256;
        int m = idx >> 3, kc = idx & 7;
        uint32_t dst = st + (uint32_t)(m * 128) + (uint32_t)((kc << 4) ^ ((m & 7) << 4));
        cpasync16(dst, Asrc + (size_t)m * HDIM + kc * 8);
    }
#pragma unroll
    for (int t = 0; t < 2; t++) {        // Bg
        int idx = tid + t * 256;
        int k = idx >> 3, nc = idx & 7;
        uint32_t dst = st + F_AB + (uint32_t)(k * 128) + (uint32_t)((nc << 4) ^ ((k & 7) << 4));
        cpasync16(dst, Bgs + (size_t)k * NPAD + nc * 8);
    }
#pragma unroll
    for (int t = 0; t < 2; t++) {        // Bu
        int idx = tid + t * 256;
        int k = idx >> 3, nc = idx & 7;
        uint32_t dst = st + F_AB + F_BB + (uint32_t)(k * 128) + (uint32_t)((nc << 4) ^ ((k & 7) << 4));
        cpasync16(dst, Bus + (size_t)k * NPAD + nc * 8);
    }
}

__global__ void __launch_bounds__(256) gemm_fused12(
    const float* __restrict__ bg, const float* __restrict__ bu)
{
    extern __shared__ __align__(1024) char dsm[];
    uint32_t sbase = smem_u32(dsm);
    int tid = threadIdx.x, wid = tid >> 5, lane = tid & 31;
    int gp = lane >> 2, tg = lane & 3;
    int wm = (wid >> 1) * 32;            // 4 warp rows
    int wn = (wid & 1) * 32;             // 2 warp cols
    int bm = blockIdx.y * 128, bn = blockIdx.x * 64;

    const __half* Ag = d_Xg + (size_t)bm * HDIM;
    const __half* Bg = d_Wg + bn;
    const __half* Bu = d_Wu + bn;
    const int NC = HDIM >> 6;            // 32

    float cg[2][4][4], cu[2][4][4];
#pragma unroll
    for (int mi = 0; mi < 2; mi++)
#pragma unroll
        for (int ni = 0; ni < 4; ni++)
#pragma unroll
            for (int q = 0; q < 4; q++) { cg[mi][ni][q] = 0.f; cu[mi][ni][q] = 0.f; }

    load_stage12(sbase,         Ag, Bg, Bu, 0, tid); CP_COMMIT();
    load_stage12(sbase + F_STG, Ag, Bg, Bu, 1, tid); CP_COMMIT();

    int mat = lane >> 3, r8 = lane & 7;

    for (int i = 0; i < NC; i++) {
        CP_WAIT1();
        __syncthreads();
        if (i + 2 < NC) load_stage12(sbase + ((i + 2) % NS) * F_STG, Ag, Bg, Bu, i + 2, tid);
        CP_COMMIT();

        uint32_t abase = sbase + (i % NS) * F_STG;
        uint32_t gbase = abase + F_AB;
        uint32_t ubase = gbase + F_BB;

#pragma unroll
        for (int ks = 0; ks < 4; ks++) {
            int kk = ks * 16;
            uint32_t a[2][4], bG[4][2], bU[4][2];
#pragma unroll
            for (int mi = 0; mi < 2; mi++) {
                int m = wm + mi * 16 + r8 + (mat & 1) * 8;
                int kc = (kk >> 3) + (mat >> 1);
                uint32_t addr = abase + (uint32_t)(m * 128) + (uint32_t)((kc << 4) ^ ((m & 7) << 4));
                ldm_x4(a[mi], addr);
            }
            int kq = kk + (mat & 1) * 8 + r8;
#pragma unroll
            for (int nj = 0; nj < 2; nj++) {
                int n = wn + nj * 16 + (mat >> 1) * 8;
                uint32_t off = (uint32_t)(kq * 128) + (uint32_t)((((n >> 3) & 7) << 4) ^ ((kq & 7) << 4));
                uint32_t t4[4];
                ldm_x4_t(t4, gbase + off);
                bG[nj * 2 + 0][0] = t4[0]; bG[nj * 2 + 0][1] = t4[1];
                bG[nj * 2 + 1][0] = t4[2]; bG[nj * 2 + 1][1] = t4[3];
                ldm_x4_t(t4, ubase + off);
                bU[nj * 2 + 0][0] = t4[0]; bU[nj * 2 + 0][1] = t4[1];
                bU[nj * 2 + 1][0] = t4[2]; bU[nj * 2 + 1][1] = t4[3];
            }
#pragma unroll
            for (int mi = 0; mi < 2; mi++)
#pragma unroll
                for (int ni = 0; ni < 4; ni++) {
                    mma16816(cg[mi][ni], a[mi], bG[ni]);
                    mma16816(cu[mi][ni], a[mi], bU[ni]);
                }
        }
    }

    // epilogue: silu(gate+bg)*(up+bu) -> d_Hh (pad cols zeroed)
#pragma unroll
    for (int mi = 0; mi < 2; mi++) {
        int row = bm + wm + mi * 16 + gp;
#pragma unroll
        for (int ni = 0; ni < 4; ni++) {
            int col = bn + wn + ni * 8 + 2 * tg;
            float b0g = 0.f, b1g = 0.f, b0u = 0.f, b1u = 0.f;
            bool v0 = col < DFF, v1 = (col + 1) < DFF;
            if (v0) { b0g = bg[col];     b0u = bu[col]; }
            if (v1) { b1g = bg[col + 1]; b1u = bu[col + 1]; }
#pragma unroll
            for (int h = 0; h < 2; h++) {
                int r2 = row + h * 8;
                float o0 = 0.f, o1 = 0.f;
                if (v0) {
                    float gate = cg[mi][ni][h * 2 + 0] + b0g;
                    float up   = cu[mi][ni][h * 2 + 0] + b0u;
                    o0 = gate * (1.0f / (1.0f + expf(-gate))) * up;
                }
                if (v1) {
                    float gate = cg[mi][ni][h * 2 + 1] + b1g;
                    float up   = cu[mi][ni][h * 2 + 1] + b1u;
                    o1 = gate * (1.0f / (1.0f + expf(-gate))) * up;
                }
                *(__half2*)(d_Hh + (size_t)r2 * NPAD + col) = __floats2half2_rn(o0, o1);
            }
        }
    }
}

// =============== GEMM3: Hh * Wd -> atomicAdd(out) (round-9 body) ===============
// CTA 128x128, BK=64, NS=3, 256 thr (8 warps: 2M x 4N), warp tile 64x32.
#define ABYTES 16384            // 128 x 64 half
#define STG3   32768            // + B 64 x 128 half

__device__ __forceinline__ void load_stage3(uint32_t st, const __half* Ag,
                                            const __half* Bg, int i, int tid) {
    const __half* Asrc = Ag + i * 64;
    const __half* Bsrc = Bg + (size_t)(i * 64) * HDIM;
#pragma unroll
    for (int t = 0; t < 4; t++) {
        int idx = tid + t * 256;
        int m = idx >> 3, kc = idx & 7;
        uint32_t dst = st + (uint32_t)(m * 128) + (uint32_t)((kc << 4) ^ ((m & 7) << 4));
        cpasync16(dst, Asrc + (size_t)m * NPAD + kc * 8);
    }
#pragma unroll
    for (int t = 0; t < 4; t++) {
        int idx = tid + t * 256;
        int k = idx >> 4, nc = idx & 15;
        uint32_t dst = st + (uint32_t)ABYTES + (uint32_t)(k * 256) + (uint32_t)((nc & 8) << 4)
                     + (uint32_t)(((nc & 7) << 4) ^ ((k & 7) << 4));
        cpasync16(dst, Bsrc + (size_t)k * HDIM + nc * 8);
    }
}

__global__ void __launch_bounds__(256) gemm3(
    const float* __restrict__ bdn, float* __restrict__ out)
{
    extern __shared__ __align__(1024) char dsm[];
    uint32_t sbase = smem_u32(dsm);
    int tid = threadIdx.x, wid = tid >> 5, lane = tid & 31;
    int gp = lane >> 2, tg = lane & 3;
    int wm = (wid >> 2) * 64;
    int wn = (wid & 3) * 32;
    int bm = blockIdx.y * 128, bn = blockIdx.x * 128;

    const __half* Ag = d_Hh + (size_t)bm * NPAD;
    const __half* Bg = d_Wd + bn;
    const int NC = NPAD >> 6;    // 86

    float c[4][4][4];
#pragma unroll
    for (int mi = 0; mi < 4; mi++)
#pragma unroll
        for (int ni = 0; ni < 4; ni++)
#pragma unroll
            for (int q = 0; q < 4; q++) c[mi][ni][q] = 0.0f;

    load_stage3(sbase,        Ag, Bg, 0, tid); CP_COMMIT();
    load_stage3(sbase + STG3, Ag, Bg, 1, tid); CP_COMMIT();

    int mat = lane >> 3, r8 = lane & 7;

    for (int i = 0; i < NC; i++) {
        CP_WAIT1();
        __syncthreads();
        if (i + 2 < NC) load_stage3(sbase + ((i + 2) % NS) * STG3, Ag, Bg, i + 2, tid);
        CP_COMMIT();

        uint32_t abase = sbase + (i % NS) * STG3;
        uint32_t bbase = abase + ABYTES;

#pragma unroll
        for (int ks = 0; ks < 4; ks++) {
            int kk = ks * 16;
            uint32_t a[4][4], b[4][2];
#pragma unroll
            for (int mi = 0; mi < 4; mi++) {
                int m = wm + mi * 16 + r8 + (mat & 1) * 8;
                int kc = (kk >> 3) + (mat >> 1);
                uint32_t addr = abase + (uint32_t)(m * 128) + (uint32_t)((kc << 4) ^ ((m & 7) << 4));
                ldm_x4(a[mi], addr);
            }
#pragma unroll
            for (int nj = 0; nj < 2; nj++) {
                int kq = kk + (mat & 1) * 8 + r8;
                int n  = wn + nj * 16 + (mat >> 1) * 8;
                uint32_t addr = bbase + (uint32_t)(kq * 256) + (uint32_t)((n & 64) << 1)
                              + (uint32_t)(((((n >> 3) & 7) << 4)) ^ ((kq & 7) << 4));
                uint32_t t4[4];
                ldm_x4_t(t4, addr);
                b[nj * 2 + 0][0] = t4[0]; b[nj * 2 + 0][1] = t4[1];
                b[nj * 2 + 1][0] = t4[2]; b[nj * 2 + 1][1] = t4[3];
            }
#pragma unroll
            for (int mi = 0; mi < 4; mi++)
#pragma unroll
                for (int ni = 0; ni < 4; ni++)
                    mma16816(c[mi][ni], a[mi], b[ni]);
        }
    }

#pragma unroll
    for (int mi = 0; mi < 4; mi++) {
        int row = bm + wm + mi * 16 + gp;
        int tok0 = d_idx[row];     float g0 = d_G[row];
        int tok1 = d_idx[row + 8]; float g1 = d_G[row + 8];
#pragma unroll
        for (int ni = 0; ni < 4; ni++) {
            int col = bn + wn + ni * 8 + 2 * tg;
            float b0 = bdn[col], b1 = bdn[col + 1];
            float* o0 = out + (size_t)tok0 * HDIM + col;
            atomicAdd(o0,     g0 * (c[mi][ni][0] + b0));
            atomicAdd(o0 + 1, g0 * (c[mi][ni][1] + b1));
            float* o1 = out + (size_t)tok1 * HDIM + col;
            atomicAdd(o1,     g1 * (c[mi][ni][2] + b0));
            atomicAdd(o1 + 1, g1 * (c[mi][ni][3] + b1));
        }
    }
}

// ---------------- launch ----------------
extern "C" void kernel_launch(void* const* d_in, const int* in_sizes, int n_in,
                              void* d_out, int out_size) {
    const float* x  = (const float*)d_in[0];
    const float* rw = (const float*)d_in[1];
    const float* rb = (const float*)d_in[2];
    const float* wg = (const float*)d_in[3];
    const float* bg = (const float*)d_in[4];
    const float* wu = (const float*)d_in[5];
    const float* bu = (const float*)d_in[6];
    const float* wd = (const float*)d_in[7];
    const float* bd = (const float*)d_in[8];
    float* out = (float*)d_out;

    cudaFuncSetAttribute(gemm_fused12, cudaFuncAttributeMaxDynamicSharedMemorySize, DYN);
    cudaFuncSetAttribute(gemm3,        cudaFuncAttributeMaxDynamicSharedMemorySize, DYN);

    prologue_kernel<<<NB_TOTAL, 256>>>(x, rw, rb, wg, wu, wd, out);

    rank_topk_kernel<<<64, 1024>>>();
    gather_kernel<<<NSLOT, 256>>>(x);

    dim3 g12(NPAD / 64, NSLOT / 128);    // (86, 64)
    gemm_fused12<<<g12, 256, DYN>>>(bg, bu);

    dim3 g3(HDIM / 128, NSLOT / 128);    // (16, 64)
    gemm3<<<g3, 256, DYN>>>(bd, out);
}

// round 15
// speedup vs baseline: 1.0479x; 1.0039x over previous
#include <cuda_runtime.h>
#include <cuda_fp16.h>
#include <cstdint>
#include <cstddef>

#define NTOK 8192
#define HDIM 2048
#define NEXP 8
#define KCAP 1024
#define DFF  5461
#define NPAD 5504
#define NSLOT 8192   // NEXP * KCAP

// ---------------- device scratch (static, no allocations) ----------------
__device__ float  d_Sm [NEXP * NTOK];            // transposed: [expert][token]
__device__ int    d_cnt[NEXP];
__device__ int    d_idx[NSLOT];
__device__ float  d_G  [NSLOT];
__device__ __half d_Xg [(size_t)NSLOT * HDIM];   // gathered tokens fp16
__device__ __half d_Wg [(size_t)HDIM * NPAD];    // w_gate  [K=2048][N=5504] fp16
__device__ __half d_Wu [(size_t)HDIM * NPAD];    // w_up
__device__ __half d_Wd [(size_t)NPAD * HDIM];    // w_down  [K=5504][N=2048] fp16
__device__ __half d_Hh [(size_t)NSLOT * NPAD];   // silu(g)*up fp16

// ---------------- helpers ----------------
__device__ __forceinline__ uint32_t smem_u32(const void* p) {
    uint32_t a;
    asm("{ .reg .u64 t; cvta.to.shared.u64 t, %1; cvt.u32.u64 %0, t; }" : "=r"(a) : "l"(p));
    return a;
}
__device__ __forceinline__ void cpasync16(uint32_t dst, const void* src) {
    asm volatile("cp.async.cg.shared.global [%0], [%1], 16;" :: "r"(dst), "l"(src) : "memory");
}
#define CP_COMMIT()  asm volatile("cp.async.commit_group;" ::: "memory")
#define CP_WAIT1()   asm volatile("cp.async.wait_group 1;" ::: "memory")

__device__ __forceinline__ void ldm_x4(uint32_t* r, uint32_t a) {
    asm volatile("ldmatrix.sync.aligned.m8n8.x4.shared.b16 {%0,%1,%2,%3}, [%4];"
                 : "=r"(r[0]), "=r"(r[1]), "=r"(r[2]), "=r"(r[3]) : "r"(a));
}
__device__ __forceinline__ void ldm_x4_t(uint32_t* r, uint32_t a) {
    asm volatile("ldmatrix.sync.aligned.m8n8.x4.trans.shared.b16 {%0,%1,%2,%3}, [%4];"
                 : "=r"(r[0]), "=r"(r[1]), "=r"(r[2]), "=r"(r[3]) : "r"(a));
}
__device__ __forceinline__ void mma16816(float* c, const uint32_t* a, const uint32_t* b) {
    asm volatile(
        "mma.sync.aligned.m16n8k16.row.col.f32.f16.f16.f32 "
        "{%0,%1,%2,%3}, {%4,%5,%6,%7}, {%8,%9}, {%0,%1,%2,%3};"
        : "+f"(c[0]), "+f"(c[1]), "+f"(c[2]), "+f"(c[3])
        : "r"(a[0]), "r"(a[1]), "r"(a[2]), "r"(a[3]), "r"(b[0]), "r"(b[1]));
}

// ================= fused prologue megakernel =================
#define NB_R 1024                        // router: 8 tokens per block
#define NB_Z (NTOK * HDIM / 4 / 256)     // 16384 float4 zero blocks
#define NB_W (HDIM * NPAD / 8 / 256)     // 5504 blocks per weight tensor
#define NB_TOTAL (NB_R + NB_Z + 3 * NB_W)

__global__ void __launch_bounds__(256) prologue_kernel(
    const float* __restrict__ x,  const float* __restrict__ rw,
    const float* __restrict__ rb, const float* __restrict__ wg,
    const float* __restrict__ wu, const float* __restrict__ wd,
    float* __restrict__ out)
{
    int b = blockIdx.x;
    int tid = threadIdx.x;

    if (b < NB_R) {
        // ---------- router section ----------
        if (b == 0 && tid < NEXP) d_cnt[tid] = 0;
        int gw = b * 8 + (tid >> 5);
        int lane = tid & 31;

        float gum = 0.0f;
        if (lane < NEXP) {
            unsigned i = (unsigned)gw * NEXP + lane;
            const uint32_t ks0 = 0u, ks1 = 42u, ks2 = 0u ^ 42u ^ 0x1BD11BDAu;
            uint32_t x0 = 0u + ks0;
            uint32_t x1 = i  + ks1;
#define TF_RND(r) { x0 += x1; x1 = (x1 << (r)) | (x1 >> (32 - (r))); x1 ^= x0; }
            TF_RND(13) TF_RND(15) TF_RND(26) TF_RND(6)   x0 += ks1; x1 += ks2 + 1u;
            TF_RND(17) TF_RND(29) TF_RND(16) TF_RND(24)  x0 += ks2; x1 += ks0 + 2u;
            TF_RND(13) TF_RND(15) TF_RND(26) TF_RND(6)   x0 += ks0; x1 += ks1 + 3u;
            TF_RND(17) TF_RND(29) TF_RND(16) TF_RND(24)  x0 += ks1; x1 += ks2 + 4u;
            TF_RND(13) TF_RND(15) TF_RND(26) TF_RND(6)   x0 += ks2; x1 += ks0 + 5u;
#undef TF_RND
            uint32_t bits = x0 ^ x1;
            float u = __uint_as_float((bits >> 9) | 0x3F800000u) - 1.0f;
            gum = -logf(-logf(u + 1e-10f) + 1e-10f);
        }

        const float* xr = x + (size_t)gw * HDIM;
        float acc[NEXP];
#pragma unroll
        for (int e = 0; e < NEXP; e++) acc[e] = 0.0f;
        for (int h = lane; h < HDIM; h += 32) {
            float xv = xr[h];
            const float4* w4 = (const float4*)(rw + (size_t)h * NEXP);
            float4 w0 = w4[0], w1 = w4[1];
            acc[0] += xv * w0.x; acc[1] += xv * w0.y;
            acc[2] += xv * w0.z; acc[3] += xv * w0.w;
            acc[4] += xv * w1.x; acc[5] += xv * w1.y;
            acc[6] += xv * w1.z; acc[7] += xv * w1.w;
        }
        double da[NEXP];
#pragma unroll
        for (int e = 0; e < NEXP; e++) da[e] = (double)acc[e];
#pragma unroll
        for (int off = 16; off; off >>= 1)
#pragma unroll
            for (int e = 0; e < NEXP; e++)
                da[e] += __shfl_xor_sync(0xffffffffu, da[e], off);
        float gv[NEXP];
#pragma unroll
        for (int e = 0; e < NEXP; e++) gv[e] = __shfl_sync(0xffffffffu, gum, e);
        if (lane == 0) {
            float hh[NEXP]; float mx = -1e30f;
#pragma unroll
            for (int e = 0; e < NEXP; e++) {
                hh[e] = (float)da[e] + rb[e] + gv[e];
                mx = fmaxf(mx, hh[e]);
            }
            float s = 0.0f;
#pragma unroll
            for (int e = 0; e < NEXP; e++) { hh[e] = expf(hh[e] - mx); s += hh[e]; }
            float inv = 1.0f / s;
#pragma unroll
            for (int e = 0; e < NEXP; e++) d_Sm[(size_t)e * NTOK + gw] = hh[e] * inv;
        }
        return;
    }
    b -= NB_R;

    if (b < NB_Z) {
        size_t i = (size_t)b * 256 + tid;
        ((float4*)out)[i] = make_float4(0.f, 0.f, 0.f, 0.f);
        return;
    }
    b -= NB_Z;

    if (b < 2 * NB_W) {
        const float* src = (b < NB_W) ? wg : wu;
        __half* dst = (b < NB_W) ? d_Wg : d_Wu;
        int i = (b % NB_W) * 256 + tid;
        int r = i / (NPAD / 8), c = (i - r * (NPAD / 8)) * 8;
        const float* s = src + (size_t)r * DFF + c;
        __half h[8];
#pragma unroll
        for (int q = 0; q < 8; q++)
            h[q] = (c + q < DFF) ? __float2half_rn(__ldg(s + q)) : __half(0.f);
        *(uint4*)(dst + (size_t)r * NPAD + c) = *(uint4*)h;
        return;
    }
    b -= 2 * NB_W;

    {
        int i = b * 256 + tid;
        int r = i / (HDIM / 8), c = (i - r * (HDIM / 8)) * 8;
        __half h[8];
        if (r < DFF) {
            const float* s = wd + (size_t)r * HDIM + c;
            float4 v0 = *(const float4*)s, v1 = *(const float4*)(s + 4);
            h[0]=__float2half_rn(v0.x); h[1]=__float2half_rn(v0.y);
            h[2]=__float2half_rn(v0.z); h[3]=__float2half_rn(v0.w);
            h[4]=__float2half_rn(v1.x); h[5]=__float2half_rn(v1.y);
            h[6]=__float2half_rn(v1.z); h[7]=__float2half_rn(v1.w);
        } else {
#pragma unroll
            for (int q = 0; q < 8; q++) h[q] = __half(0.f);
        }
        *(uint4*)(d_Wd + (size_t)r * HDIM + c) = *(uint4*)h;
    }
}

// ---------------- rank-select top-k ----------------
__global__ void __launch_bounds__(1024) rank_topk_kernel() {
    __shared__ float sval[NTOK];
    int e = blockIdx.x >> 3;
    int chunk = blockIdx.x & 7;
    int tid = threadIdx.x;
    const float* Se = d_Sm + (size_t)e * NTOK;
    for (int i = tid; i < NTOK; i += 1024) sval[i] = Se[i];
    __syncthreads();
    int t = chunk * 1024 + tid;
    float v = sval[t];
    int rank = 0;
#pragma unroll 8
    for (int j = 0; j < NTOK; j++) {
        float vj = sval[j];
        rank += (vj > v) || (vj == v && j < t);
    }
    if (rank < KCAP) {
        int pos = atomicAdd(&d_cnt[e], 1);
        d_idx[e * KCAP + pos] = t;
        d_G[e * KCAP + pos]   = v;
    }
}

// ---------------- gather routed tokens -> fp16 ----------------
__global__ void gather_kernel(const float* __restrict__ x) {
    int r = blockIdx.x;
    int tok = d_idx[r];
    const float4* src = (const float4*)(x + (size_t)tok * HDIM);
    __half2* dst = (__half2*)(d_Xg + (size_t)r * HDIM);
    for (int i = threadIdx.x; i < HDIM / 4; i += blockDim.x) {
        float4 v = src[i];
        dst[i * 2]     = __floats2half2_rn(v.x, v.y);
        dst[i * 2 + 1] = __floats2half2_rn(v.z, v.w);
    }
}

// =============== fused GEMM1+2: Xg*[Wg|Wu] -> silu -> d_Hh ===============
// CTA 128(M) x 64(N), two B tensors. BK=64, NS=3, 256 thr (8 warps: 4M x 2N),
// warp tile 32x32 per output tensor. Loop-invariant fragment addresses hoisted
// into registers (aoff/boff) -> inner loop does one IADD per ldmatrix.
#define F_AB   16384                 // A 128x64 half
#define F_BB   8192                  // each B 64x64 half
#define F_STG  (F_AB + 2 * F_BB)     // 32768
#define NS     3
#define DYN    (NS * F_STG)          // 98304

__device__ __forceinline__ void load_stage12(uint32_t st, const __half* Ag,
                                             const __half* Bg, const __half* Bu,
                                             int i, int tid) {
    const __half* Asrc = Ag + i * 64;
    const __half* Bgs = Bg + (size_t)(i * 64) * NPAD;
    const __half* Bus = Bu + (size_t)(i * 64) * NPAD;
#pragma unroll
    for (int t = 0; t < 4; t++) {        // A: 128 rows x 8 chunks
        int idx = tid + t * 256;
        int m = idx >> 3, kc = idx & 7;
        uint32_t dst = st + (uint32_t)(m * 128) + (uint32_t)((kc << 4) ^ ((m & 7) << 4));
        cpasync16(dst, Asrc + (size_t)m * HDIM + kc * 8);
    }
#pragma unroll
    for (int t = 0; t < 2; t++) {        // Bg
        int idx = tid + t * 256;
        int k = idx >> 3, nc = idx & 7;
        uint32_t dst = st + F_AB + (uint32_t)(k * 128) + (uint32_t)((nc << 4) ^ ((k & 7) << 4));
        cpasync16(dst, Bgs + (size_t)k * NPAD + nc * 8);
    }
#pragma unroll
    for (int t = 0; t < 2; t++) {        // Bu
        int idx = tid + t * 256;
        int k = idx >> 3, nc = idx & 7;
        uint32_t dst = st + F_AB + F_BB + (uint32_t)(k * 128) + (uint32_t)((nc << 4) ^ ((k & 7) << 4));
        cpasync16(dst, Bus + (size_t)k * NPAD + nc * 8);
    }
}

__global__ void __launch_bounds__(256) gemm_fused12(
    const float* __restrict__ bg, const float* __restrict__ bu)
{
    extern __shared__ __align__(1024) char dsm[];
    uint32_t sbase = smem_u32(dsm);
    int tid = threadIdx.x, wid = tid >> 5, lane = tid & 31;
    int gp = lane >> 2, tg = lane & 3;
    int wm = (wid >> 1) * 32;            // 4 warp rows
    int wn = (wid & 1) * 32;             // 2 warp cols
    int bm = blockIdx.y * 128, bn = blockIdx.x * 64;

    const __half* Ag = d_Xg + (size_t)bm * HDIM;
    const __half* Bg = d_Wg + bn;
    const __half* Bu = d_Wu + bn;
    const int NC = HDIM >> 6;            // 32

    int mat = lane >> 3, r8 = lane & 7;

    // ---- hoisted loop-invariant fragment offsets (relative to stage base) ----
    uint32_t aoff[2][4], boff[2][4];
#pragma unroll
    for (int mi = 0; mi < 2; mi++)
#pragma unroll
        for (int ks = 0; ks < 4; ks++) {
            int m = wm + mi * 16 + r8 + (mat & 1) * 8;
            int kc = ks * 2 + (mat >> 1);
            aoff[mi][ks] = (uint32_t)(m * 128) + (uint32_t)((kc << 4) ^ ((m & 7) << 4));
        }
#pragma unroll
    for (int nj = 0; nj < 2; nj++)
#pragma unroll
        for (int ks = 0; ks < 4; ks++) {
            int kq = ks * 16 + (mat & 1) * 8 + r8;
            int n = wn + nj * 16 + (mat >> 1) * 8;
            boff[nj][ks] = (uint32_t)(kq * 128)
                         + (uint32_t)((((n >> 3) & 7) << 4) ^ ((kq & 7) << 4));
        }

    float cg[2][4][4], cu[2][4][4];
#pragma unroll
    for (int mi = 0; mi < 2; mi++)
#pragma unroll
        for (int ni = 0; ni < 4; ni++)
#pragma unroll
            for (int q = 0; q < 4; q++) { cg[mi][ni][q] = 0.f; cu[mi][ni][q] = 0.f; }

    load_stage12(sbase,         Ag, Bg, Bu, 0, tid); CP_COMMIT();
    load_stage12(sbase + F_STG, Ag, Bg, Bu, 1, tid); CP_COMMIT();

    for (int i = 0; i < NC; i++) {
        CP_WAIT1();
        __syncthreads();
        if (i + 2 < NC) load_stage12(sbase + ((i + 2) % NS) * F_STG, Ag, Bg, Bu, i + 2, tid);
        CP_COMMIT();

        uint32_t abase = sbase + (i % NS) * F_STG;
        uint32_t gbase = abase + F_AB;
        uint32_t ubase = gbase + F_BB;

#pragma unroll
        for (int ks = 0; ks < 4; ks++) {
            uint32_t a[2][4], bG[4][2], bU[4][2];
#pragma unroll
            for (int mi = 0; mi < 2; mi++)
                ldm_x4(a[mi], abase + aoff[mi][ks]);
#pragma unroll
            for (int nj = 0; nj < 2; nj++) {
                uint32_t t4[4];
                ldm_x4_t(t4, gbase + boff[nj][ks]);
                bG[nj * 2 + 0][0] = t4[0]; bG[nj * 2 + 0][1] = t4[1];
                bG[nj * 2 + 1][0] = t4[2]; bG[nj * 2 + 1][1] = t4[3];
                ldm_x4_t(t4, ubase + boff[nj][ks]);
                bU[nj * 2 + 0][0] = t4[0]; bU[nj * 2 + 0][1] = t4[1];
                bU[nj * 2 + 1][0] = t4[2]; bU[nj * 2 + 1][1] = t4[3];
            }
#pragma unroll
            for (int mi = 0; mi < 2; mi++)
#pragma unroll
                for (int ni = 0; ni < 4; ni++) {
                    mma16816(cg[mi][ni], a[mi], bG[ni]);
                    mma16816(cu[mi][ni], a[mi], bU[ni]);
                }
        }
    }

    // epilogue: silu(gate+bg)*(up+bu) -> d_Hh (pad cols zeroed)
#pragma unroll
    for (int mi = 0; mi < 2; mi++) {
        int row = bm + wm + mi * 16 + gp;
#pragma unroll
        for (int ni = 0; ni < 4; ni++) {
            int col = bn + wn + ni * 8 + 2 * tg;
            float b0g = 0.f, b1g = 0.f, b0u = 0.f, b1u = 0.f;
            bool v0 = col < DFF, v1 = (col + 1) < DFF;
            if (v0) { b0g = bg[col];     b0u = bu[col]; }
            if (v1) { b1g = bg[col + 1]; b1u = bu[col + 1]; }
#pragma unroll
            for (int h = 0; h < 2; h++) {
                int r2 = row + h * 8;
                float o0 = 0.f, o1 = 0.f;
                if (v0) {
                    float gate = cg[mi][ni][h * 2 + 0] + b0g;
                    float up   = cu[mi][ni][h * 2 + 0] + b0u;
                    o0 = gate * (1.0f / (1.0f + expf(-gate))) * up;
                }
                if (v1) {
                    float gate = cg[mi][ni][h * 2 + 1] + b1g;
                    float up   = cu[mi][ni][h * 2 + 1] + b1u;
                    o1 = gate * (1.0f / (1.0f + expf(-gate))) * up;
                }
                *(__half2*)(d_Hh + (size_t)r2 * NPAD + col) = __floats2half2_rn(o0, o1);
            }
        }
    }
}

// =============== GEMM3: Hh * Wd -> atomicAdd(out) (round-9/14 body, unchanged) ===============
#define ABYTES 16384            // 128 x 64 half
#define STG3   32768            // + B 64 x 128 half

__device__ __forceinline__ void load_stage3(uint32_t st, const __half* Ag,
                                            const __half* Bg, int i, int tid) {
    const __half* Asrc = Ag + i * 64;
    const __half* Bsrc = Bg + (size_t)(i * 64) * HDIM;
#pragma unroll
    for (int t = 0; t < 4; t++) {
        int idx = tid + t * 256;
        int m = idx >> 3, kc = idx & 7;
        uint32_t dst = st + (uint32_t)(m * 128) + (uint32_t)((kc << 4) ^ ((m & 7) << 4));
        cpasync16(dst, Asrc + (size_t)m * NPAD + kc * 8);
    }
#pragma unroll
    for (int t = 0; t < 4; t++) {
        int idx = tid + t * 256;
        int k = idx >> 4, nc = idx & 15;
        uint32_t dst = st + (uint32_t)ABYTES + (uint32_t)(k * 256) + (uint32_t)((nc & 8) << 4)
                     + (uint32_t)(((nc & 7) << 4) ^ ((k & 7) << 4));
        cpasync16(dst, Bsrc + (size_t)k * HDIM + nc * 8);
    }
}

__global__ void __launch_bounds__(256) gemm3(
    const float* __restrict__ bdn, float* __restrict__ out)
{
    extern __shared__ __align__(1024) char dsm[];
    uint32_t sbase = smem_u32(dsm);
    int tid = threadIdx.x, wid = tid >> 5, lane = tid & 31;
    int gp = lane >> 2, tg = lane & 3;
    int wm = (wid >> 2) * 64;
    int wn = (wid & 3) * 32;
    int bm = blockIdx.y * 128, bn = blockIdx.x * 128;

    const __half* Ag = d_Hh + (size_t)bm * NPAD;
    const __half* Bg = d_Wd + bn;
    const int NC = NPAD >> 6;    // 86

    float c[4][4][4];
#pragma unroll
    for (int mi = 0; mi < 4; mi++)
#pragma unroll
        for (int ni = 0; ni < 4; ni++)
#pragma unroll
            for (int q = 0; q < 4; q++) c[mi][ni][q] = 0.0f;

    load_stage3(sbase,        Ag, Bg, 0, tid); CP_COMMIT();
    load_stage3(sbase + STG3, Ag, Bg, 1, tid); CP_COMMIT();

    int mat = lane >> 3, r8 = lane & 7;

    for (int i = 0; i < NC; i++) {
        CP_WAIT1();
        __syncthreads();
        if (i + 2 < NC) load_stage3(sbase + ((i + 2) % NS) * STG3, Ag, Bg, i + 2, tid);
        CP_COMMIT();

        uint32_t abase = sbase + (i % NS) * STG3;
        uint32_t bbase = abase + ABYTES;

#pragma unroll
        for (int ks = 0; ks < 4; ks++) {
            int kk = ks * 16;
            uint32_t a[4][4], b[4][2];
#pragma unroll
            for (int mi = 0; mi < 4; mi++) {
                int m = wm + mi * 16 + r8 + (mat & 1) * 8;
                int kc = (kk >> 3) + (mat >> 1);
                uint32_t addr = abase + (uint32_t)(m * 128) + (uint32_t)((kc << 4) ^ ((m & 7) << 4));
                ldm_x4(a[mi], addr);
            }
#pragma unroll
            for (int nj = 0; nj < 2; nj++) {
                int kq = kk + (mat & 1) * 8 + r8;
                int n  = wn + nj * 16 + (mat >> 1) * 8;
                uint32_t addr = bbase + (uint32_t)(kq * 256) + (uint32_t)((n & 64) << 1)
                              + (uint32_t)(((((n >> 3) & 7) << 4)) ^ ((kq & 7) << 4));
                uint32_t t4[4];
                ldm_x4_t(t4, addr);
                b[nj * 2 + 0][0] = t4[0]; b[nj * 2 + 0][1] = t4[1];
                b[nj * 2 + 1][0] = t4[2]; b[nj * 2 + 1][1] = t4[3];
            }
#pragma unroll
            for (int mi = 0; mi < 4; mi++)
#pragma unroll
                for (int ni = 0; ni < 4; ni++)
                    mma16816(c[mi][ni], a[mi], b[ni]);
        }
    }

#pragma unroll
    for (int mi = 0; mi < 4; mi++) {
        int row = bm + wm + mi * 16 + gp;
        int tok0 = d_idx[row];     float g0 = d_G[row];
        int tok1 = d_idx[row + 8]; float g1 = d_G[row + 8];
#pragma unroll
        for (int ni = 0; ni < 4; ni++) {
            int col = bn + wn + ni * 8 + 2 * tg;
            float b0 = bdn[col], b1 = bdn[col + 1];
            float* o0 = out + (size_t)tok0 * HDIM + col;
            atomicAdd(o0,     g0 * (c[mi][ni][0] + b0));
            atomicAdd(o0 + 1, g0 * (c[mi][ni][1] + b1));
            float* o1 = out + (size_t)tok1 * HDIM + col;
            atomicAdd(o1,     g1 * (c[mi][ni][2] + b0));
            atomicAdd(o1 + 1, g1 * (c[mi][ni][3] + b1));
        }
    }
}

// ---------------- launch ----------------
extern "C" void kernel_launch(void* const* d_in, const int* in_sizes, int n_in,
                              void* d_out, int out_size) {
    const float* x  = (const float*)d_in[0];
    const float* rw = (const float*)d_in[1];
    const float* rb = (const float*)d_in[2];
    const float* wg = (const float*)d_in[3];
    const float* bg = (const float*)d_in[4];
    const float* wu = (const float*)d_in[5];
    const float* bu = (const float*)d_in[6];
    const float* wd = (const float*)d_in[7];
    const float* bd = (const float*)d_in[8];
    float* out = (float*)d_out;

    cudaFuncSetAttribute(gemm_fused12, cudaFuncAttributeMaxDynamicSharedMemorySize, DYN);
    cudaFuncSetAttribute(gemm3,        cudaFuncAttributeMaxDynamicSharedMemorySize, DYN);

    prologue_kernel<<<NB_TOTAL, 256>>>(x, rw, rb, wg, wu, wd, out);

    rank_topk_kernel<<<64, 1024>>>();
    gather_kernel<<<NSLOT, 256>>>(x);

    dim3 g12(NPAD / 64, NSLOT / 128);    // (86, 64)
    gemm_fused12<<<g12, 256, DYN>>>(bg, bu);

    dim3 g3(HDIM / 128, NSLOT / 128);    // (16, 64)
    gemm3<<<g3, 256, DYN>>>(bd, out);
}

// round 16
// speedup vs baseline: 1.0612x; 1.0127x over previous
#include <cuda_runtime.h>
#include <cuda_fp16.h>
#include <cstdint>
#include <cstddef>

#define NTOK 8192
#define HDIM 2048
#define NEXP 8
#define KCAP 1024
#define DFF  5461
#define NPAD 5504
#define NSLOT 8192   // NEXP * KCAP

// ---------------- device scratch (static, no allocations) ----------------
__device__ float  d_Sm [NEXP * NTOK];            // transposed: [expert][token]
__device__ int    d_cnt[NEXP];
__device__ int    d_idx[NSLOT];
__device__ float  d_G  [NSLOT];
__device__ __half d_Xg [(size_t)NSLOT * HDIM];   // gathered tokens fp16
__device__ __half d_Wg [(size_t)HDIM * NPAD];    // w_gate  [K=2048][N=5504] fp16
__device__ __half d_Wu [(size_t)HDIM * NPAD];    // w_up
__device__ __half d_Wd [(size_t)NPAD * HDIM];    // w_down  [K=5504][N=2048] fp16
__device__ __half d_Hh [(size_t)NSLOT * NPAD];   // silu(g)*up fp16

// ---------------- helpers ----------------
__device__ __forceinline__ uint32_t smem_u32(const void* p) {
    uint32_t a;
    asm("{ .reg .u64 t; cvta.to.shared.u64 t, %1; cvt.u32.u64 %0, t; }" : "=r"(a) : "l"(p));
    return a;
}
__device__ __forceinline__ void cpasync16(uint32_t dst, const void* src) {
    asm volatile("cp.async.cg.shared.global [%0], [%1], 16;" :: "r"(dst), "l"(src) : "memory");
}
#define CP_COMMIT()  asm volatile("cp.async.commit_group;" ::: "memory")
#define CP_WAIT1()   asm volatile("cp.async.wait_group 1;" ::: "memory")

__device__ __forceinline__ void ldm_x4(uint32_t* r, uint32_t a) {
    asm volatile("ldmatrix.sync.aligned.m8n8.x4.shared.b16 {%0,%1,%2,%3}, [%4];"
                 : "=r"(r[0]), "=r"(r[1]), "=r"(r[2]), "=r"(r[3]) : "r"(a));
}
__device__ __forceinline__ void ldm_x4_t(uint32_t* r, uint32_t a) {
    asm volatile("ldmatrix.sync.aligned.m8n8.x4.trans.shared.b16 {%0,%1,%2,%3}, [%4];"
                 : "=r"(r[0]), "=r"(r[1]), "=r"(r[2]), "=r"(r[3]) : "r"(a));
}
__device__ __forceinline__ void mma16816(float* c, const uint32_t* a, const uint32_t* b) {
    asm volatile(
        "mma.sync.aligned.m16n8k16.row.col.f32.f16.f16.f32 "
        "{%0,%1,%2,%3}, {%4,%5,%6,%7}, {%8,%9}, {%0,%1,%2,%3};"
        : "+f"(c[0]), "+f"(c[1]), "+f"(c[2]), "+f"(c[3])
        : "r"(a[0]), "r"(a[1]), "r"(a[2]), "r"(a[3]), "r"(b[0]), "r"(b[1]));
}

// ================= fused prologue megakernel =================
#define NB_R 1024                        // router: 8 tokens per block
#define NB_Z (NTOK * HDIM / 4 / 256)     // 16384 float4 zero blocks
#define NB_W (HDIM * NPAD / 8 / 256)     // 5504 blocks per weight tensor
#define NB_TOTAL (NB_R + NB_Z + 3 * NB_W)

__global__ void __launch_bounds__(256) prologue_kernel(
    const float* __restrict__ x,  const float* __restrict__ rw,
    const float* __restrict__ rb, const float* __restrict__ wg,
    const float* __restrict__ wu, const float* __restrict__ wd,
    float* __restrict__ out)
{
    int b = blockIdx.x;
    int tid = threadIdx.x;

    if (b < NB_R) {
        // ---------- router section ----------
        if (b == 0 && tid < NEXP) d_cnt[tid] = 0;
        int gw = b * 8 + (tid >> 5);
        int lane = tid & 31;

        float gum = 0.0f;
        if (lane < NEXP) {
            unsigned i = (unsigned)gw * NEXP + lane;
            const uint32_t ks0 = 0u, ks1 = 42u, ks2 = 0u ^ 42u ^ 0x1BD11BDAu;
            uint32_t x0 = 0u + ks0;
            uint32_t x1 = i  + ks1;
#define TF_RND(r) { x0 += x1; x1 = (x1 << (r)) | (x1 >> (32 - (r))); x1 ^= x0; }
            TF_RND(13) TF_RND(15) TF_RND(26) TF_RND(6)   x0 += ks1; x1 += ks2 + 1u;
            TF_RND(17) TF_RND(29) TF_RND(16) TF_RND(24)  x0 += ks2; x1 += ks0 + 2u;
            TF_RND(13) TF_RND(15) TF_RND(26) TF_RND(6)   x0 += ks0; x1 += ks1 + 3u;
            TF_RND(17) TF_RND(29) TF_RND(16) TF_RND(24)  x0 += ks1; x1 += ks2 + 4u;
            TF_RND(13) TF_RND(15) TF_RND(26) TF_RND(6)   x0 += ks2; x1 += ks0 + 5u;
#undef TF_RND
            uint32_t bits = x0 ^ x1;
            float u = __uint_as_float((bits >> 9) | 0x3F800000u) - 1.0f;
            gum = -logf(-logf(u + 1e-10f) + 1e-10f);
        }

        const float* xr = x + (size_t)gw * HDIM;
        float acc[NEXP];
#pragma unroll
        for (int e = 0; e < NEXP; e++) acc[e] = 0.0f;
        for (int h = lane; h < HDIM; h += 32) {
            float xv = xr[h];
            const float4* w4 = (const float4*)(rw + (size_t)h * NEXP);
            float4 w0 = w4[0], w1 = w4[1];
            acc[0] += xv * w0.x; acc[1] += xv * w0.y;
            acc[2] += xv * w0.z; acc[3] += xv * w0.w;
            acc[4] += xv * w1.x; acc[5] += xv * w1.y;
            acc[6] += xv * w1.z; acc[7] += xv * w1.w;
        }
        double da[NEXP];
#pragma unroll
        for (int e = 0; e < NEXP; e++) da[e] = (double)acc[e];
#pragma unroll
        for (int off = 16; off; off >>= 1)
#pragma unroll
            for (int e = 0; e < NEXP; e++)
                da[e] += __shfl_xor_sync(0xffffffffu, da[e], off);
        float gv[NEXP];
#pragma unroll
        for (int e = 0; e < NEXP; e++) gv[e] = __shfl_sync(0xffffffffu, gum, e);
        if (lane == 0) {
            float hh[NEXP]; float mx = -1e30f;
#pragma unroll
            for (int e = 0; e < NEXP; e++) {
                hh[e] = (float)da[e] + rb[e] + gv[e];
                mx = fmaxf(mx, hh[e]);
            }
            float s = 0.0f;
#pragma unroll
            for (int e = 0; e < NEXP; e++) { hh[e] = expf(hh[e] - mx); s += hh[e]; }
            float inv = 1.0f / s;
#pragma unroll
            for (int e = 0; e < NEXP; e++) d_Sm[(size_t)e * NTOK + gw] = hh[e] * inv;
        }
        return;
    }
    b -= NB_R;

    if (b < NB_Z) {
        size_t i = (size_t)b * 256 + tid;
        ((float4*)out)[i] = make_float4(0.f, 0.f, 0.f, 0.f);
        return;
    }
    b -= NB_Z;

    if (b < 2 * NB_W) {
        const float* src = (b < NB_W) ? wg : wu;
        __half* dst = (b < NB_W) ? d_Wg : d_Wu;
        int i = (b % NB_W) * 256 + tid;
        int r = i / (NPAD / 8), c = (i - r * (NPAD / 8)) * 8;
        const float* s = src + (size_t)r * DFF + c;
        __half h[8];
#pragma unroll
        for (int q = 0; q < 8; q++)
            h[q] = (c + q < DFF) ? __float2half_rn(__ldg(s + q)) : __half(0.f);
        *(uint4*)(dst + (size_t)r * NPAD + c) = *(uint4*)h;
        return;
    }
    b -= 2 * NB_W;

    {
        int i = b * 256 + tid;
        int r = i / (HDIM / 8), c = (i - r * (HDIM / 8)) * 8;
        __half h[8];
        if (r < DFF) {
            const float* s = wd + (size_t)r * HDIM + c;
            float4 v0 = *(const float4*)s, v1 = *(const float4*)(s + 4);
            h[0]=__float2half_rn(v0.x); h[1]=__float2half_rn(v0.y);
            h[2]=__float2half_rn(v0.z); h[3]=__float2half_rn(v0.w);
            h[4]=__float2half_rn(v1.x); h[5]=__float2half_rn(v1.y);
            h[6]=__float2half_rn(v1.z); h[7]=__float2half_rn(v1.w);
        } else {
#pragma unroll
            for (int q = 0; q < 8; q++) h[q] = __half(0.f);
        }
        *(uint4*)(d_Wd + (size_t)r * HDIM + c) = *(uint4*)h;
    }
}

// ---------------- rank-select top-k (float4 smem fill) ----------------
__global__ void __launch_bounds__(1024) rank_topk_kernel() {
    __shared__ float sval[NTOK];
    int e = blockIdx.x >> 3;
    int chunk = blockIdx.x & 7;
    int tid = threadIdx.x;
    const float4* Se4 = (const float4*)(d_Sm + (size_t)e * NTOK);
    for (int i = tid; i < NTOK / 4; i += 1024)
        *(float4*)(sval + i * 4) = Se4[i];
    __syncthreads();
    int t = chunk * 1024 + tid;
    float v = sval[t];
    int rank = 0;
#pragma unroll 8
    for (int j = 0; j < NTOK; j++) {
        float vj = sval[j];
        rank += (vj > v) || (vj == v && j < t);
    }
    if (rank < KCAP) {
        int pos = atomicAdd(&d_cnt[e], 1);
        d_idx[e * KCAP + pos] = t;
        d_G[e * KCAP + pos]   = v;
    }
}

// ---------------- gather routed tokens -> fp16 ----------------
__global__ void gather_kernel(const float* __restrict__ x) {
    int r = blockIdx.x;
    int tok = d_idx[r];
    const float4* src = (const float4*)(x + (size_t)tok * HDIM);
    __half2* dst = (__half2*)(d_Xg + (size_t)r * HDIM);
    for (int i = threadIdx.x; i < HDIM / 4; i += blockDim.x) {
        float4 v = src[i];
        dst[i * 2]     = __floats2half2_rn(v.x, v.y);
        dst[i * 2 + 1] = __floats2half2_rn(v.z, v.w);
    }
}

// =============== fused GEMM1+2: Xg*[Wg|Wu] -> silu -> d_Hh ===============
// CTA 128(M) x 64(N), two B tensors. BK=64, NS=3, 256 thr (8 warps: 4M x 2N),
// warp tile 32x32 per output tensor. Hoisted fragment offsets.
#define F_AB   16384                 // A 128x64 half
#define F_BB   8192                  // each B 64x64 half
#define F_STG  (F_AB + 2 * F_BB)     // 32768
#define NS     3
#define DYN    (NS * F_STG)          // 98304

__device__ __forceinline__ void load_stage12(uint32_t st, const __half* Ag,
                                             const __half* Bg, const __half* Bu,
                                             int i, int tid) {
    const __half* Asrc = Ag + i * 64;
    const __half* Bgs = Bg + (size_t)(i * 64) * NPAD;
    const __half* Bus = Bu + (size_t)(i * 64) * NPAD;
#pragma unroll
    for (int t = 0; t < 4; t++) {        // A: 128 rows x 8 chunks
        int idx = tid + t * 256;
        int m = idx >> 3, kc = idx & 7;
        uint32_t dst = st + (uint32_t)(m * 128) + (uint32_t)((kc << 4) ^ ((m & 7) << 4));
        cpasync16(dst, Asrc + (size_t)m * HDIM + kc * 8);
    }
#pragma unroll
    for (int t = 0; t < 2; t++) {        // Bg
        int idx = tid + t * 256;
        int k = idx >> 3, nc = idx & 7;
        uint32_t dst = st + F_AB + (uint32_t)(k * 128) + (uint32_t)((nc << 4) ^ ((k & 7) << 4));
        cpasync16(dst, Bgs + (size_t)k * NPAD + nc * 8);
    }
#pragma unroll
    for (int t = 0; t < 2; t++) {        // Bu
        int idx = tid + t * 256;
        int k = idx >> 3, nc = idx & 7;
        uint32_t dst = st + F_AB + F_BB + (uint32_t)(k * 128) + (uint32_t)((nc << 4) ^ ((k & 7) << 4));
        cpasync16(dst, Bus + (size_t)k * NPAD + nc * 8);
    }
}

__global__ void __launch_bounds__(256) gemm_fused12(
    const float* __restrict__ bg, const float* __restrict__ bu)
{
    extern __shared__ __align__(1024) char dsm[];
    uint32_t sbase = smem_u32(dsm);
    int tid = threadIdx.x, wid = tid >> 5, lane = tid & 31;
    int gp = lane >> 2, tg = lane & 3;
    int wm = (wid >> 1) * 32;            // 4 warp rows
    int wn = (wid & 1) * 32;             // 2 warp cols
    int bm = blockIdx.y * 128, bn = blockIdx.x * 64;

    const __half* Ag = d_Xg + (size_t)bm * HDIM;
    const __half* Bg = d_Wg + bn;
    const __half* Bu = d_Wu + bn;
    const int NC = HDIM >> 6;            // 32

    int mat = lane >> 3, r8 = lane & 7;

    uint32_t aoff[2][4], boff[2][4];
#pragma unroll
    for (int mi = 0; mi < 2; mi++)
#pragma unroll
        for (int ks = 0; ks < 4; ks++) {
            int m = wm + mi * 16 + r8 + (mat & 1) * 8;
            int kc = ks * 2 + (mat >> 1);
            aoff[mi][ks] = (uint32_t)(m * 128) + (uint32_t)((kc << 4) ^ ((m & 7) << 4));
        }
#pragma unroll
    for (int nj = 0; nj < 2; nj++)
#pragma unroll
        for (int ks = 0; ks < 4; ks++) {
            int kq = ks * 16 + (mat & 1) * 8 + r8;
            int n = wn + nj * 16 + (mat >> 1) * 8;
            boff[nj][ks] = (uint32_t)(kq * 128)
                         + (uint32_t)((((n >> 3) & 7) << 4) ^ ((kq & 7) << 4));
        }

    float cg[2][4][4], cu[2][4][4];
#pragma unroll
    for (int mi = 0; mi < 2; mi++)
#pragma unroll
        for (int ni = 0; ni < 4; ni++)
#pragma unroll
            for (int q = 0; q < 4; q++) { cg[mi][ni][q] = 0.f; cu[mi][ni][q] = 0.f; }

    load_stage12(sbase,         Ag, Bg, Bu, 0, tid); CP_COMMIT();
    load_stage12(sbase + F_STG, Ag, Bg, Bu, 1, tid); CP_COMMIT();

    for (int i = 0; i < NC; i++) {
        CP_WAIT1();
        __syncthreads();
        if (i + 2 < NC) load_stage12(sbase + ((i + 2) % NS) * F_STG, Ag, Bg, Bu, i + 2, tid);
        CP_COMMIT();

        uint32_t abase = sbase + (i % NS) * F_STG;
        uint32_t gbase = abase + F_AB;
        uint32_t ubase = gbase + F_BB;

#pragma unroll
        for (int ks = 0; ks < 4; ks++) {
            uint32_t a[2][4], bG[4][2], bU[4][2];
#pragma unroll
            for (int mi = 0; mi < 2; mi++)
                ldm_x4(a[mi], abase + aoff[mi][ks]);
#pragma unroll
            for (int nj = 0; nj < 2; nj++) {
                uint32_t t4[4];
                ldm_x4_t(t4, gbase + boff[nj][ks]);
                bG[nj * 2 + 0][0] = t4[0]; bG[nj * 2 + 0][1] = t4[1];
                bG[nj * 2 + 1][0] = t4[2]; bG[nj * 2 + 1][1] = t4[3];
                ldm_x4_t(t4, ubase + boff[nj][ks]);
                bU[nj * 2 + 0][0] = t4[0]; bU[nj * 2 + 0][1] = t4[1];
                bU[nj * 2 + 1][0] = t4[2]; bU[nj * 2 + 1][1] = t4[3];
            }
#pragma unroll
            for (int mi = 0; mi < 2; mi++)
#pragma unroll
                for (int ni = 0; ni < 4; ni++) {
                    mma16816(cg[mi][ni], a[mi], bG[ni]);
                    mma16816(cu[mi][ni], a[mi], bU[ni]);
                }
        }
    }

    // epilogue: silu(gate+bg)*(up+bu) -> d_Hh (pad cols zeroed)
#pragma unroll
    for (int mi = 0; mi < 2; mi++) {
        int row = bm + wm + mi * 16 + gp;
#pragma unroll
        for (int ni = 0; ni < 4; ni++) {
            int col = bn + wn + ni * 8 + 2 * tg;
            float b0g = 0.f, b1g = 0.f, b0u = 0.f, b1u = 0.f;
            bool v0 = col < DFF, v1 = (col + 1) < DFF;
            if (v0) { b0g = bg[col];     b0u = bu[col]; }
            if (v1) { b1g = bg[col + 1]; b1u = bu[col + 1]; }
#pragma unroll
            for (int h = 0; h < 2; h++) {
                int r2 = row + h * 8;
                float o0 = 0.f, o1 = 0.f;
                if (v0) {
                    float gate = cg[mi][ni][h * 2 + 0] + b0g;
                    float up   = cu[mi][ni][h * 2 + 0] + b0u;
                    o0 = gate * (1.0f / (1.0f + expf(-gate))) * up;
                }
                if (v1) {
                    float gate = cg[mi][ni][h * 2 + 1] + b1g;
                    float up   = cu[mi][ni][h * 2 + 1] + b1u;
                    o1 = gate * (1.0f / (1.0f + expf(-gate))) * up;
                }
                *(__half2*)(d_Hh + (size_t)r2 * NPAD + col) = __floats2half2_rn(o0, o1);
            }
        }
    }
}

// =============== GEMM3: Hh * Wd -> atomicAdd(out) ===============
// CTA 128x128, BK=64, NS=3, 256 thr (8 warps: 2M x 4N), warp tile 64x32.
// Hoisted fragment offsets (mirror of fused12's verified win).
#define ABYTES 16384            // 128 x 64 half
#define STG3   32768            // + B 64 x 128 half

__device__ __forceinline__ void load_stage3(uint32_t st, const __half* Ag,
                                            const __half* Bg, int i, int tid) {
    const __half* Asrc = Ag + i * 64;
    const __half* Bsrc = Bg + (size_t)(i * 64) * HDIM;
#pragma unroll
    for (int t = 0; t < 4; t++) {
        int idx = tid + t * 256;
        int m = idx >> 3, kc = idx & 7;
        uint32_t dst = st + (uint32_t)(m * 128) + (uint32_t)((kc << 4) ^ ((m & 7) << 4));
        cpasync16(dst, Asrc + (size_t)m * NPAD + kc * 8);
    }
#pragma unroll
    for (int t = 0; t < 4; t++) {
        int idx = tid + t * 256;
        int k = idx >> 4, nc = idx & 15;
        uint32_t dst = st + (uint32_t)ABYTES + (uint32_t)(k * 256) + (uint32_t)((nc & 8) << 4)
                     + (uint32_t)(((nc & 7) << 4) ^ ((k & 7) << 4));
        cpasync16(dst, Bsrc + (size_t)k * HDIM + nc * 8);
    }
}

__global__ void __launch_bounds__(256) gemm3(
    const float* __restrict__ bdn, float* __restrict__ out)
{
    extern __shared__ __align__(1024) char dsm[];
    uint32_t sbase = smem_u32(dsm);
    int tid = threadIdx.x, wid = tid >> 5, lane = tid & 31;
    int gp = lane >> 2, tg = lane & 3;
    int wm = (wid >> 2) * 64;
    int wn = (wid & 3) * 32;
    int bm = blockIdx.y * 128, bn = blockIdx.x * 128;

    const __half* Ag = d_Hh + (size_t)bm * NPAD;
    const __half* Bg = d_Wd + bn;
    const int NC = NPAD >> 6;    // 86

    int mat = lane >> 3, r8 = lane & 7;

    // ---- hoisted loop-invariant fragment offsets ----
    uint32_t aoff[4][4], boff[2][4];
#pragma unroll
    for (int mi = 0; mi < 4; mi++)
#pragma unroll
        for (int ks = 0; ks < 4; ks++) {
            int m = wm + mi * 16 + r8 + (mat & 1) * 8;
            int kc = ks * 2 + (mat >> 1);
            aoff[mi][ks] = (uint32_t)(m * 128) + (uint32_t)((kc << 4) ^ ((m & 7) << 4));
        }
#pragma unroll
    for (int nj = 0; nj < 2; nj++)
#pragma unroll
        for (int ks = 0; ks < 4; ks++) {
            int kq = ks * 16 + (mat & 1) * 8 + r8;
            int n  = wn + nj * 16 + (mat >> 1) * 8;
            boff[nj][ks] = (uint32_t)(kq * 256) + (uint32_t)((n & 64) << 1)
                         + (uint32_t)((((n >> 3) & 7) << 4) ^ ((kq & 7) << 4));
        }

    float c[4][4][4];
#pragma unroll
    for (int mi = 0; mi < 4; mi++)
#pragma unroll
        for (int ni = 0; ni < 4; ni++)
#pragma unroll
            for (int q = 0; q < 4; q++) c[mi][ni][q] = 0.0f;

    load_stage3(sbase,        Ag, Bg, 0, tid); CP_COMMIT();
    load_stage3(sbase + STG3, Ag, Bg, 1, tid); CP_COMMIT();

    for (int i = 0; i < NC; i++) {
        CP_WAIT1();
        __syncthreads();
        if (i + 2 < NC) load_stage3(sbase + ((i + 2) % NS) * STG3, Ag, Bg, i + 2, tid);
        CP_COMMIT();

        uint32_t abase = sbase + (i % NS) * STG3;
        uint32_t bbase = abase + ABYTES;

#pragma unroll
        for (int ks = 0; ks < 4; ks++) {
            uint32_t a[4][4], b[4][2];
#pragma unroll
            for (int mi = 0; mi < 4; mi++)
                ldm_x4(a[mi], abase + aoff[mi][ks]);
#pragma unroll
            for (int nj = 0; nj < 2; nj++) {
                uint32_t t4[4];
                ldm_x4_t(t4, bbase + boff[nj][ks]);
                b[nj * 2 + 0][0] = t4[0]; b[nj * 2 + 0][1] = t4[1];
                b[nj * 2 + 1][0] = t4[2]; b[nj * 2 + 1][1] = t4[3];
            }
#pragma unroll
            for (int mi = 0; mi < 4; mi++)
#pragma unroll
                for (int ni = 0; ni < 4; ni++)
                    mma16816(c[mi][ni], a[mi], b[ni]);
        }
    }

#pragma unroll
    for (int mi = 0; mi < 4; mi++) {
        int row = bm + wm + mi * 16 + gp;
        int tok0 = d_idx[row];     float g0 = d_G[row];
        int tok1 = d_idx[row + 8]; float g1 = d_G[row + 8];
#pragma unroll
        for (int ni = 0; ni < 4; ni++) {
            int col = bn + wn + ni * 8 + 2 * tg;
            float b0 = bdn[col], b1 = bdn[col + 1];
            float* o0 = out + (size_t)tok0 * HDIM + col;
            atomicAdd(o0,     g0 * (c[mi][ni][0] + b0));
            atomicAdd(o0 + 1, g0 * (c[mi][ni][1] + b1));
            float* o1 = out + (size_t)tok1 * HDIM + col;
            atomicAdd(o1,     g1 * (c[mi][ni][2] + b0));
            atomicAdd(o1 + 1, g1 * (c[mi][ni][3] + b1));
        }
    }
}

// ---------------- launch ----------------
extern "C" void kernel_launch(void* const* d_in, const int* in_sizes, int n_in,
                              void* d_out, int out_size) {
    const float* x  = (const float*)d_in[0];
    const float* rw = (const float*)d_in[1];
    const float* rb = (const float*)d_in[2];
    const float* wg = (const float*)d_in[3];
    const float* bg = (const float*)d_in[4];
    const float* wu = (const float*)d_in[5];
    const float* bu = (const float*)d_in[6];
    const float* wd = (const float*)d_in[7];
    const float* bd = (const float*)d_in[8];
    float* out = (float*)d_out;

    cudaFuncSetAttribute(gemm_fused12, cudaFuncAttributeMaxDynamicSharedMemorySize, DYN);
    cudaFuncSetAttribute(gemm3,        cudaFuncAttributeMaxDynamicSharedMemorySize, DYN);

    prologue_kernel<<<NB_TOTAL, 256>>>(x, rw, rb, wg, wu, wd, out);

    rank_topk_kernel<<<64, 1024>>>();
    gather_kernel<<<NSLOT, 256>>>(x);

    dim3 g12(NPAD / 64, NSLOT / 128);    // (86, 64)
    gemm_fused12<<<g12, 256, DYN>>>(bg, bu);

    dim3 g3(HDIM / 128, NSLOT / 128);    // (16, 64)
    gemm3<<<g3, 256, DYN>>>(bd, out);
}

// round 17
// speedup vs baseline: 1.1200x; 1.0554x over previous
#include <cuda_runtime.h>
#include <cuda_fp16.h>
#include <cstdint>
#include <cstddef>

#define NTOK 8192
#define HDIM 2048
#define NEXP 8
#define KCAP 1024
#define DFF  5461
#define NPAD 5504
#define NSLOT 8192   // NEXP * KCAP

// ---------------- device scratch (static, no allocations) ----------------
__device__ float  d_Sm [NEXP * NTOK];            // transposed: [expert][token]
__device__ int    d_cnt[NEXP];
__device__ int    d_idx[NSLOT];
__device__ float  d_G  [NSLOT];
__device__ __half d_Xg [(size_t)NSLOT * HDIM];   // gathered tokens fp16
__device__ __half d_Wg [(size_t)HDIM * NPAD];    // w_gate  [K=2048][N=5504] fp16
__device__ __half d_Wu [(size_t)HDIM * NPAD];    // w_up
__device__ __half d_Wd [(size_t)NPAD * HDIM];    // w_down  [K=5504][N=2048] fp16
__device__ __half d_Hh [(size_t)NSLOT * NPAD];   // silu(g)*up fp16

// ---------------- helpers ----------------
__device__ __forceinline__ uint32_t smem_u32(const void* p) {
    uint32_t a;
    asm("{ .reg .u64 t; cvta.to.shared.u64 t, %1; cvt.u32.u64 %0, t; }" : "=r"(a) : "l"(p));
    return a;
}
__device__ __forceinline__ void cpasync16(uint32_t dst, const void* src) {
    asm volatile("cp.async.cg.shared.global [%0], [%1], 16;" :: "r"(dst), "l"(src) : "memory");
}
#define CP_COMMIT()  asm volatile("cp.async.commit_group;" ::: "memory")
#define CP_WAIT1()   asm volatile("cp.async.wait_group 1;" ::: "memory")

__device__ __forceinline__ void ldm_x4(uint32_t* r, uint32_t a) {
    asm volatile("ldmatrix.sync.aligned.m8n8.x4.shared.b16 {%0,%1,%2,%3}, [%4];"
                 : "=r"(r[0]), "=r"(r[1]), "=r"(r[2]), "=r"(r[3]) : "r"(a));
}
__device__ __forceinline__ void ldm_x4_t(uint32_t* r, uint32_t a) {
    asm volatile("ldmatrix.sync.aligned.m8n8.x4.trans.shared.b16 {%0,%1,%2,%3}, [%4];"
                 : "=r"(r[0]), "=r"(r[1]), "=r"(r[2]), "=r"(r[3]) : "r"(a));
}
__device__ __forceinline__ void mma16816(float* c, const uint32_t* a, const uint32_t* b) {
    asm volatile(
        "mma.sync.aligned.m16n8k16.row.col.f32.f16.f16.f32 "
        "{%0,%1,%2,%3}, {%4,%5,%6,%7}, {%8,%9}, {%0,%1,%2,%3};"
        : "+f"(c[0]), "+f"(c[1]), "+f"(c[2]), "+f"(c[3])
        : "r"(a[0]), "r"(a[1]), "r"(a[2]), "r"(a[3]), "r"(b[0]), "r"(b[1]));
}

// ================= fused prologue megakernel =================
#define NB_R 1024                        // router: 8 tokens per block
#define NB_Z (NTOK * HDIM / 4 / 256)     // 16384 float4 zero blocks
#define NB_W (HDIM * NPAD / 8 / 256)     // 5504 blocks per weight tensor
#define NB_TOTAL (NB_R + NB_Z + 3 * NB_W)

__global__ void __launch_bounds__(256) prologue_kernel(
    const float* __restrict__ x,  const float* __restrict__ rw,
    const float* __restrict__ rb, const float* __restrict__ wg,
    const float* __restrict__ wu, const float* __restrict__ wd,
    float* __restrict__ out)
{
    int b = blockIdx.x;
    int tid = threadIdx.x;

    if (b < NB_R) {
        // ---------- router section ----------
        if (b == 0 && tid < NEXP) d_cnt[tid] = 0;
        int gw = b * 8 + (tid >> 5);
        int lane = tid & 31;

        float gum = 0.0f;
        if (lane < NEXP) {
            unsigned i = (unsigned)gw * NEXP + lane;
            const uint32_t ks0 = 0u, ks1 = 42u, ks2 = 0u ^ 42u ^ 0x1BD11BDAu;
            uint32_t x0 = 0u + ks0;
            uint32_t x1 = i  + ks1;
#define TF_RND(r) { x0 += x1; x1 = (x1 << (r)) | (x1 >> (32 - (r))); x1 ^= x0; }
            TF_RND(13) TF_RND(15) TF_RND(26) TF_RND(6)   x0 += ks1; x1 += ks2 + 1u;
            TF_RND(17) TF_RND(29) TF_RND(16) TF_RND(24)  x0 += ks2; x1 += ks0 + 2u;
            TF_RND(13) TF_RND(15) TF_RND(26) TF_RND(6)   x0 += ks0; x1 += ks1 + 3u;
            TF_RND(17) TF_RND(29) TF_RND(16) TF_RND(24)  x0 += ks1; x1 += ks2 + 4u;
            TF_RND(13) TF_RND(15) TF_RND(26) TF_RND(6)   x0 += ks2; x1 += ks0 + 5u;
#undef TF_RND
            uint32_t bits = x0 ^ x1;
            float u = __uint_as_float((bits >> 9) | 0x3F800000u) - 1.0f;
            gum = -logf(-logf(u + 1e-10f) + 1e-10f);
        }

        const float* xr = x + (size_t)gw * HDIM;
        float acc[NEXP];
#pragma unroll
        for (int e = 0; e < NEXP; e++) acc[e] = 0.0f;
        for (int h = lane; h < HDIM; h += 32) {
            float xv = xr[h];
            const float4* w4 = (const float4*)(rw + (size_t)h * NEXP);
            float4 w0 = w4[0], w1 = w4[1];
            acc[0] += xv * w0.x; acc[1] += xv * w0.y;
            acc[2] += xv * w0.z; acc[3] += xv * w0.w;
            acc[4] += xv * w1.x; acc[5] += xv * w1.y;
            acc[6] += xv * w1.z; acc[7] += xv * w1.w;
        }
        double da[NEXP];
#pragma unroll
        for (int e = 0; e < NEXP; e++) da[e] = (double)acc[e];
#pragma unroll
        for (int off = 16; off; off >>= 1)
#pragma unroll
            for (int e = 0; e < NEXP; e++)
                da[e] += __shfl_xor_sync(0xffffffffu, da[e], off);
        float gv[NEXP];
#pragma unroll
        for (int e = 0; e < NEXP; e++) gv[e] = __shfl_sync(0xffffffffu, gum, e);
        if (lane == 0) {
            float hh[NEXP]; float mx = -1e30f;
#pragma unroll
            for (int e = 0; e < NEXP; e++) {
                hh[e] = (float)da[e] + rb[e] + gv[e];
                mx = fmaxf(mx, hh[e]);
            }
            float s = 0.0f;
#pragma unroll
            for (int e = 0; e < NEXP; e++) { hh[e] = expf(hh[e] - mx); s += hh[e]; }
            float inv = 1.0f / s;
#pragma unroll
            for (int e = 0; e < NEXP; e++) d_Sm[(size_t)e * NTOK + gw] = hh[e] * inv;
        }
        return;
    }
    b -= NB_R;

    if (b < NB_Z) {
        size_t i = (size_t)b * 256 + tid;
        ((float4*)out)[i] = make_float4(0.f, 0.f, 0.f, 0.f);
        return;
    }
    b -= NB_Z;

    if (b < 2 * NB_W) {
        const float* src = (b < NB_W) ? wg : wu;
        __half* dst = (b < NB_W) ? d_Wg : d_Wu;
        int i = (b % NB_W) * 256 + tid;
        int r = i / (NPAD / 8), c = (i - r * (NPAD / 8)) * 8;
        const float* s = src + (size_t)r * DFF + c;
        __half h[8];
#pragma unroll
        for (int q = 0; q < 8; q++)
            h[q] = (c + q < DFF) ? __float2half_rn(__ldg(s + q)) : __half(0.f);
        *(uint4*)(dst + (size_t)r * NPAD + c) = *(uint4*)h;
        return;
    }
    b -= 2 * NB_W;

    {
        int i = b * 256 + tid;
        int r = i / (HDIM / 8), c = (i - r * (HDIM / 8)) * 8;
        __half h[8];
        if (r < DFF) {
            const float* s = wd + (size_t)r * HDIM + c;
            float4 v0 = *(const float4*)s, v1 = *(const float4*)(s + 4);
            h[0]=__float2half_rn(v0.x); h[1]=__float2half_rn(v0.y);
            h[2]=__float2half_rn(v0.z); h[3]=__float2half_rn(v0.w);
            h[4]=__float2half_rn(v1.x); h[5]=__float2half_rn(v1.y);
            h[6]=__float2half_rn(v1.z); h[7]=__float2half_rn(v1.w);
        } else {
#pragma unroll
            for (int q = 0; q < 8; q++) h[q] = __half(0.f);
        }
        *(uint4*)(d_Wd + (size_t)r * HDIM + c) = *(uint4*)h;
    }
}

// ---------------- rank-select top-k: float4 scan, 128 CTAs x 512 thr ----------------
// 16 chunks x 8 experts; <=1 CTA/SM (128 < 148) and 4 compares per LDS.128.
__global__ void __launch_bounds__(512) rank_topk_kernel() {
    __shared__ float sval[NTOK];
    int e = blockIdx.x >> 4;
    int chunk = blockIdx.x & 15;
    int tid = threadIdx.x;
    const float4* Se4 = (const float4*)(d_Sm + (size_t)e * NTOK);
    float4* sv4 = (float4*)sval;
    for (int i = tid; i < NTOK / 4; i += 512)
        sv4[i] = Se4[i];
    __syncthreads();
    int t = chunk * 512 + tid;
    float v = sval[t];
    int rank = 0;
#pragma unroll 4
    for (int j4 = 0; j4 < NTOK / 4; j4++) {
        float4 q = sv4[j4];
        int j = j4 << 2;
        rank += (q.x > v) || (q.x == v && j < t);
        rank += (q.y > v) || (q.y == v && (j + 1) < t);
        rank += (q.z > v) || (q.z == v && (j + 2) < t);
        rank += (q.w > v) || (q.w == v && (j + 3) < t);
    }
    if (rank < KCAP) {
        int pos = atomicAdd(&d_cnt[e], 1);
        d_idx[e * KCAP + pos] = t;
        d_G[e * KCAP + pos]   = v;
    }
}

// ---------------- gather routed tokens -> fp16 ----------------
__global__ void gather_kernel(const float* __restrict__ x) {
    int r = blockIdx.x;
    int tok = d_idx[r];
    const float4* src = (const float4*)(x + (size_t)tok * HDIM);
    __half2* dst = (__half2*)(d_Xg + (size_t)r * HDIM);
    for (int i = threadIdx.x; i < HDIM / 4; i += blockDim.x) {
        float4 v = src[i];
        dst[i * 2]     = __floats2half2_rn(v.x, v.y);
        dst[i * 2 + 1] = __floats2half2_rn(v.z, v.w);
    }
}

// =============== fused GEMM1+2: Xg*[Wg|Wu] -> silu -> d_Hh ===============
// CTA 128(M) x 64(N), two B tensors. BK=64, NS=3, 256 thr (8 warps: 4M x 2N),
// warp tile 32x32 per output tensor. Hoisted fragment offsets.
#define F_AB   16384                 // A 128x64 half
#define F_BB   8192                  // each B 64x64 half
#define F_STG  (F_AB + 2 * F_BB)     // 32768
#define NS     3
#define DYN    (NS * F_STG)          // 98304

__device__ __forceinline__ void load_stage12(uint32_t st, const __half* Ag,
                                             const __half* Bg, const __half* Bu,
                                             int i, int tid) {
    const __half* Asrc = Ag + i * 64;
    const __half* Bgs = Bg + (size_t)(i * 64) * NPAD;
    const __half* Bus = Bu + (size_t)(i * 64) * NPAD;
#pragma unroll
    for (int t = 0; t < 4; t++) {        // A: 128 rows x 8 chunks
        int idx = tid + t * 256;
        int m = idx >> 3, kc = idx & 7;
        uint32_t dst = st + (uint32_t)(m * 128) + (uint32_t)((kc << 4) ^ ((m & 7) << 4));
        cpasync16(dst, Asrc + (size_t)m * HDIM + kc * 8);
    }
#pragma unroll
    for (int t = 0; t < 2; t++) {        // Bg
        int idx = tid + t * 256;
        int k = idx >> 3, nc = idx & 7;
        uint32_t dst = st + F_AB + (uint32_t)(k * 128) + (uint32_t)((nc << 4) ^ ((k & 7) << 4));
        cpasync16(dst, Bgs + (size_t)k * NPAD + nc * 8);
    }
#pragma unroll
    for (int t = 0; t < 2; t++) {        // Bu
        int idx = tid + t * 256;
        int k = idx >> 3, nc = idx & 7;
        uint32_t dst = st + F_AB + F_BB + (uint32_t)(k * 128) + (uint32_t)((nc << 4) ^ ((k & 7) << 4));
        cpasync16(dst, Bus + (size_t)k * NPAD + nc * 8);
    }
}

__global__ void __launch_bounds__(256) gemm_fused12(
    const float* __restrict__ bg, const float* __restrict__ bu)
{
    extern __shared__ __align__(1024) char dsm[];
    uint32_t sbase = smem_u32(dsm);
    int tid = threadIdx.x, wid = tid >> 5, lane = tid & 31;
    int gp = lane >> 2, tg = lane & 3;
    int wm = (wid >> 1) * 32;            // 4 warp rows
    int wn = (wid & 1) * 32;             // 2 warp cols
    int bm = blockIdx.y * 128, bn = blockIdx.x * 64;

    const __half* Ag = d_Xg + (size_t)bm * HDIM;
    const __half* Bg = d_Wg + bn;
    const __half* Bu = d_Wu + bn;
    const int NC = HDIM >> 6;            // 32

    int mat = lane >> 3, r8 = lane & 7;

    uint32_t aoff[2][4], boff[2][4];
#pragma unroll
    for (int mi = 0; mi < 2; mi++)
#pragma unroll
        for (int ks = 0; ks < 4; ks++) {
            int m = wm + mi * 16 + r8 + (mat & 1) * 8;
            int kc = ks * 2 + (mat >> 1);
            aoff[mi][ks] = (uint32_t)(m * 128) + (uint32_t)((kc << 4) ^ ((m & 7) << 4));
        }
#pragma unroll
    for (int nj = 0; nj < 2; nj++)
#pragma unroll
        for (int ks = 0; ks < 4; ks++) {
            int kq = ks * 16 + (mat & 1) * 8 + r8;
            int n = wn + nj * 16 + (mat >> 1) * 8;
            boff[nj][ks] = (uint32_t)(kq * 128)
                         + (uint32_t)((((n >> 3) & 7) << 4) ^ ((kq & 7) << 4));
        }

    float cg[2][4][4], cu[2][4][4];
#pragma unroll
    for (int mi = 0; mi < 2; mi++)
#pragma unroll
        for (int ni = 0; ni < 4; ni++)
#pragma unroll
            for (int q = 0; q < 4; q++) { cg[mi][ni][q] = 0.f; cu[mi][ni][q] = 0.f; }

    load_stage12(sbase,         Ag, Bg, Bu, 0, tid); CP_COMMIT();
    load_stage12(sbase + F_STG, Ag, Bg, Bu, 1, tid); CP_COMMIT();

    for (int i = 0; i < NC; i++) {
        CP_WAIT1();
        __syncthreads();
        if (i + 2 < NC) load_stage12(sbase + ((i + 2) % NS) * F_STG, Ag, Bg, Bu, i + 2, tid);
        CP_COMMIT();

        uint32_t abase = sbase + (i % NS) * F_STG;
        uint32_t gbase = abase + F_AB;
        uint32_t ubase = gbase + F_BB;

#pragma unroll
        for (int ks = 0; ks < 4; ks++) {
            uint32_t a[2][4], bG[4][2], bU[4][2];
#pragma unroll
            for (int mi = 0; mi < 2; mi++)
                ldm_x4(a[mi], abase + aoff[mi][ks]);
#pragma unroll
            for (int nj = 0; nj < 2; nj++) {
                uint32_t t4[4];
                ldm_x4_t(t4, gbase + boff[nj][ks]);
                bG[nj * 2 + 0][0] = t4[0]; bG[nj * 2 + 0][1] = t4[1];
                bG[nj * 2 + 1][0] = t4[2]; bG[nj * 2 + 1][1] = t4[3];
                ldm_x4_t(t4, ubase + boff[nj][ks]);
                bU[nj * 2 + 0][0] = t4[0]; bU[nj * 2 + 0][1] = t4[1];
                bU[nj * 2 + 1][0] = t4[2]; bU[nj * 2 + 1][1] = t4[3];
            }
#pragma unroll
            for (int mi = 0; mi < 2; mi++)
#pragma unroll
                for (int ni = 0; ni < 4; ni++) {
                    mma16816(cg[mi][ni], a[mi], bG[ni]);
                    mma16816(cu[mi][ni], a[mi], bU[ni]);
                }
        }
    }

    // epilogue: silu(gate+bg)*(up+bu) -> d_Hh (pad cols zeroed)
#pragma unroll
    for (int mi = 0; mi < 2; mi++) {
        int row = bm + wm + mi * 16 + gp;
#pragma unroll
        for (int ni = 0; ni < 4; ni++) {
            int col = bn + wn + ni * 8 + 2 * tg;
            float b0g = 0.f, b1g = 0.f, b0u = 0.f, b1u = 0.f;
            bool v0 = col < DFF, v1 = (col + 1) < DFF;
            if (v0) { b0g = bg[col];     b0u = bu[col]; }
            if (v1) { b1g = bg[col + 1]; b1u = bu[col + 1]; }
#pragma unroll
            for (int h = 0; h < 2; h++) {
                int r2 = row + h * 8;
                float o0 = 0.f, o1 = 0.f;
                if (v0) {
                    float gate = cg[mi][ni][h * 2 + 0] + b0g;
                    float up   = cu[mi][ni][h * 2 + 0] + b0u;
                    o0 = gate * (1.0f / (1.0f + expf(-gate))) * up;
                }
                if (v1) {
                    float gate = cg[mi][ni][h * 2 + 1] + b1g;
                    float up   = cu[mi][ni][h * 2 + 1] + b1u;
                    o1 = gate * (1.0f / (1.0f + expf(-gate))) * up;
                }
                *(__half2*)(d_Hh + (size_t)r2 * NPAD + col) = __floats2half2_rn(o0, o1);
            }
        }
    }
}

// =============== GEMM3: Hh * Wd -> atomicAdd(out) ===============
// CTA 128x128, BK=64, NS=3, 256 thr (8 warps: 2M x 4N), warp tile 64x32.
// Hoisted fragment offsets.
#define ABYTES 16384            // 128 x 64 half
#define STG3   32768            // + B 64 x 128 half

__device__ __forceinline__ void load_stage3(uint32_t st, const __half* Ag,
                                            const __half* Bg, int i, int tid) {
    const __half* Asrc = Ag + i * 64;
    const __half* Bsrc = Bg + (size_t)(i * 64) * HDIM;
#pragma unroll
    for (int t = 0; t < 4; t++) {
        int idx = tid + t * 256;
        int m = idx >> 3, kc = idx & 7;
        uint32_t dst = st + (uint32_t)(m * 128) + (uint32_t)((kc << 4) ^ ((m & 7) << 4));
        cpasync16(dst, Asrc + (size_t)m * NPAD + kc * 8);
    }
#pragma unroll
    for (int t = 0; t < 4; t++) {
        int idx = tid + t * 256;
        int k = idx >> 4, nc = idx & 15;
        uint32_t dst = st + (uint32_t)ABYTES + (uint32_t)(k * 256) + (uint32_t)((nc & 8) << 4)
                     + (uint32_t)(((nc & 7) << 4) ^ ((k & 7) << 4));
        cpasync16(dst, Bsrc + (size_t)k * HDIM + nc * 8);
    }
}

__global__ void __launch_bounds__(256) gemm3(
    const float* __restrict__ bdn, float* __restrict__ out)
{
    extern __shared__ __align__(1024) char dsm[];
    uint32_t sbase = smem_u32(dsm);
    int tid = threadIdx.x, wid = tid >> 5, lane = tid & 31;
    int gp = lane >> 2, tg = lane & 3;
    int wm = (wid >> 2) * 64;
    int wn = (wid & 3) * 32;
    int bm = blockIdx.y * 128, bn = blockIdx.x * 128;

    const __half* Ag = d_Hh + (size_t)bm * NPAD;
    const __half* Bg = d_Wd + bn;
    const int NC = NPAD >> 6;    // 86

    int mat = lane >> 3, r8 = lane & 7;

    uint32_t aoff[4][4], boff[2][4];
#pragma unroll
    for (int mi = 0; mi < 4; mi++)
#pragma unroll
        for (int ks = 0; ks < 4; ks++) {
            int m = wm + mi * 16 + r8 + (mat & 1) * 8;
            int kc = ks * 2 + (mat >> 1);
            aoff[mi][ks] = (uint32_t)(m * 128) + (uint32_t)((kc << 4) ^ ((m & 7) << 4));
        }
#pragma unroll
    for (int nj = 0; nj < 2; nj++)
#pragma unroll
        for (int ks = 0; ks < 4; ks++) {
            int kq = ks * 16 + (mat & 1) * 8 + r8;
            int n  = wn + nj * 16 + (mat >> 1) * 8;
            boff[nj][ks] = (uint32_t)(kq * 256) + (uint32_t)((n & 64) << 1)
                         + (uint32_t)((((n >> 3) & 7) << 4) ^ ((kq & 7) << 4));
        }

    float c[4][4][4];
#pragma unroll
    for (int mi = 0; mi < 4; mi++)
#pragma unroll
        for (int ni = 0; ni < 4; ni++)
#pragma unroll
            for (int q = 0; q < 4; q++) c[mi][ni][q] = 0.0f;

    load_stage3(sbase,        Ag, Bg, 0, tid); CP_COMMIT();
    load_stage3(sbase + STG3, Ag, Bg, 1, tid); CP_COMMIT();

    for (int i = 0; i < NC; i++) {
        CP_WAIT1();
        __syncthreads();
        if (i + 2 < NC) load_stage3(sbase + ((i + 2) % NS) * STG3, Ag, Bg, i + 2, tid);
        CP_COMMIT();

        uint32_t abase = sbase + (i % NS) * STG3;
        uint32_t bbase = abase + ABYTES;

#pragma unroll
        for (int ks = 0; ks < 4; ks++) {
            uint32_t a[4][4], b[4][2];
#pragma unroll
            for (int mi = 0; mi < 4; mi++)
                ldm_x4(a[mi], abase + aoff[mi][ks]);
#pragma unroll
            for (int nj = 0; nj < 2; nj++) {
                uint32_t t4[4];
                ldm_x4_t(t4, bbase + boff[nj][ks]);
                b[nj * 2 + 0][0] = t4[0]; b[nj * 2 + 0][1] = t4[1];
                b[nj * 2 + 1][0] = t4[2]; b[nj * 2 + 1][1] = t4[3];
            }
#pragma unroll
            for (int mi = 0; mi < 4; mi++)
#pragma unroll
                for (int ni = 0; ni < 4; ni++)
                    mma16816(c[mi][ni], a[mi], b[ni]);
        }
    }

#pragma unroll
    for (int mi = 0; mi < 4; mi++) {
        int row = bm + wm + mi * 16 + gp;
        int tok0 = d_idx[row];     float g0 = d_G[row];
        int tok1 = d_idx[row + 8]; float g1 = d_G[row + 8];
#pragma unroll
        for (int ni = 0; ni < 4; ni++) {
            int col = bn + wn + ni * 8 + 2 * tg;
            float b0 = bdn[col], b1 = bdn[col + 1];
            float* o0 = out + (size_t)tok0 * HDIM + col;
            atomicAdd(o0,     g0 * (c[mi][ni][0] + b0));
            atomicAdd(o0 + 1, g0 * (c[mi][ni][1] + b1));
            float* o1 = out + (size_t)tok1 * HDIM + col;
            atomicAdd(o1,     g1 * (c[mi][ni][2] + b0));
            atomicAdd(o1 + 1, g1 * (c[mi][ni][3] + b1));
        }
    }
}

// ---------------- launch ----------------
extern "C" void kernel_launch(void* const* d_in, const int* in_sizes, int n_in,
                              void* d_out, int out_size) {
    const float* x  = (const float*)d_in[0];
    const float* rw = (const float*)d_in[1];
    const float* rb = (const float*)d_in[2];
    const float* wg = (const float*)d_in[3];
    const float* bg = (const float*)d_in[4];
    const float* wu = (const float*)d_in[5];
    const float* bu = (const float*)d_in[6];
    const float* wd = (const float*)d_in[7];
    const float* bd = (const float*)d_in[8];
    float* out = (float*)d_out;

    cudaFuncSetAttribute(gemm_fused12, cudaFuncAttributeMaxDynamicSharedMemorySize, DYN);
    cudaFuncSetAttribute(gemm3,        cudaFuncAttributeMaxDynamicSharedMemorySize, DYN);

    prologue_kernel<<<NB_TOTAL, 256>>>(x, rw, rb, wg, wu, wd, out);

    rank_topk_kernel<<<128, 512>>>();
    gather_kernel<<<NSLOT, 256>>>(x);

    dim3 g12(NPAD / 64, NSLOT / 128);    // (86, 64)
    gemm_fused12<<<g12, 256, DYN>>>(bg, bu);

    dim3 g3(HDIM / 128, NSLOT / 128);    // (16, 64)
    gemm3<<<g3, 256, DYN>>>(bd, out);
}